// round 6
// baseline (speedup 1.0000x reference)
#include <cuda_runtime.h>
#include <math.h>

#define BB 32
#define NN 4096
#define CC 256
#define KK 64
#define DD 256
#define SLICES 32
#define TPS (NN/SLICES)   /* 128 tokens per CTA */
#define TCH 32            /* tokens per chunk */
#define NCH (TPS/TCH)     /* 4 chunks */
#define XS 264            /* x_s row stride: 264%32=8 -> conflict-free phases */
#define LS 36             /* logits row stride: 36%32=4 -> conflict-free softmax */
#define HCH 256           /* hidden GEMM i-chunks */
#define IC 64             /* i per hidden chunk */

typedef unsigned long long u64;

// ---------------- device scratch (no allocations allowed) ----------------
__device__ __align__(16) float  g_vpart[(size_t)BB * SLICES * KK * CC];  // 64 MB
__device__ __align__(16) float  g_apart[BB * SLICES * KK];
__device__ __align__(16) float  g_vladn[BB * KK * CC];
__device__ __align__(16) float  g_rsq[BB * KK];
__device__ __align__(16) float  g_hpart[HCH * BB * DD];                  // 8 MB
__device__ __align__(16) float  g_h[BB * DD];
__device__ __align__(16) float  g_y[BB * DD];
__device__ __align__(16) float  g_z[BB * DD];
__device__ __align__(16) float2 g_w2t[(CC/2) * KK];                      // 64 KB

// ---------------- f32x2 helpers (sm_100+ packed FFMA) ----------------
__device__ __forceinline__ u64 ffma2(u64 a, u64 b, u64 c) {
    u64 d;
    asm("fma.rn.f32x2 %0, %1, %2, %3;" : "=l"(d) : "l"(a), "l"(b), "l"(c));
    return d;
}
__device__ __forceinline__ u64 pack2(float lo, float hi) {
    u64 r;
    asm("mov.b64 %0, {%1, %2};" : "=l"(r) : "f"(lo), "f"(hi));
    return r;
}
__device__ __forceinline__ float2 unpack2(u64 v) {
    float2 f;
    asm("mov.b64 {%0, %1}, %2;" : "=f"(f.x), "=f"(f.y) : "l"(v));
    return f;
}

// =====================================================================
// Kernel 0: transpose conv_w -> w2t[c2][k] (idempotent; also used as
// launch padding so ncu's capture slot lands on k_vlad)
// =====================================================================
__global__ __launch_bounds__(256) void k_wt(const float* __restrict__ conv_w)
{
    int idx = blockIdx.x * 256 + threadIdx.x;           // 8192 total
    if (idx < (CC/2) * KK) {
        int c2 = idx >> 6, k = idx & 63;
        g_w2t[idx] = make_float2(conv_w[k * CC + 2 * c2],
                                 conv_w[k * CC + 2 * c2 + 1]);
    }
}

// =====================================================================
// Kernel 1: fused normalize + logits + softmax + VLAD partial accumulate
// grid = (SLICES, BB), block = 256, 2 CTAs/SM, smem 42KB -> w2t L1-resident
// =====================================================================
__global__ __launch_bounds__(256, 2) void k_vlad(const float* __restrict__ x)
{
    extern __shared__ float smem[];
    float* x_s = smem;                    // TCH*XS floats  (33 KB)
    float* a_s = x_s + TCH * XS;          // KK*LS floats   (9 KB)

    const int b = blockIdx.y, sl = blockIdx.x;
    const int tid = threadIdx.x;
    const int tx = tid & 15, ty = tid >> 4;

    // VLAD accumulators: thread owns k in {ty+16q}, c pairs at 2tx+32j
    u64 V2[4][8];
#pragma unroll
    for (int q = 0; q < 4; q++)
#pragma unroll
        for (int j = 0; j < 8; j++) V2[q][j] = 0ULL;
    float asum[4] = {0.f, 0.f, 0.f, 0.f};

    for (int ch = 0; ch < NCH; ++ch) {
        __syncthreads();
        const int n0 = sl * TPS + ch * TCH;
        const float* xg = x + ((size_t)b * NN + n0) * CC;
        for (int i = tid; i < TCH * CC / 4; i += 256) {
            int t = i >> 6, c4 = i & 63;
            float4 v = *(const float4*)(xg + t * CC + 4 * c4);
            *(float4*)(x_s + t * XS + 4 * c4) = v;
        }
        __syncthreads();

        // per-token L2 normalize over C (8 threads per token; TCH=32)
        {
            int t = tid >> 3, l8 = tid & 7;
            float s = 0.f;
#pragma unroll 8
            for (int c = l8; c < CC; c += 8) { float v = x_s[t * XS + c]; s = fmaf(v, v, s); }
            s += __shfl_xor_sync(0xffffffffu, s, 1);
            s += __shfl_xor_sync(0xffffffffu, s, 2);
            s += __shfl_xor_sync(0xffffffffu, s, 4);
            float inv = 1.0f / fmaxf(sqrtf(s), 1e-12f);
#pragma unroll 8
            for (int c = l8; c < CC; c += 8) x_s[t * XS + c] *= inv;
        }
        __syncthreads();

        // logits: l[k][t] = sum_c w[k][c]*xn[t][c]; 4k x 2t register tile
        // w via LDG from L1-resident w2t
        {
            u64 acc[4][2];
#pragma unroll
            for (int q = 0; q < 4; q++)
#pragma unroll
                for (int r = 0; r < 2; r++) acc[q][r] = 0ULL;
            const float2* wp0 = g_w2t + tx;
            const float* xp0 = x_s + ty * XS;
#pragma unroll 4
            for (int c2 = 0; c2 < CC / 2; ++c2) {
                u64 w2[4], x2[2];
#pragma unroll
                for (int q = 0; q < 4; q++)
                    w2[q] = *(const u64*)(wp0 + c2 * KK + 16 * q);
#pragma unroll
                for (int r = 0; r < 2; r++)
                    x2[r] = *(const u64*)(xp0 + r * 16 * XS + 2 * c2);
#pragma unroll
                for (int q = 0; q < 4; q++)
#pragma unroll
                    for (int r = 0; r < 2; r++)
                        acc[q][r] = ffma2(w2[q], x2[r], acc[q][r]);
            }
#pragma unroll
            for (int q = 0; q < 4; q++)
#pragma unroll
                for (int r = 0; r < 2; r++) {
                    float2 f = unpack2(acc[q][r]);
                    a_s[(tx + 16 * q) * LS + (ty + 16 * r)] = f.x + f.y;
                }
        }
        __syncthreads();

        // softmax over k per token (8 threads per token)
        {
            int t = tid >> 3, l8 = tid & 7;
            float mx = -1e30f;
#pragma unroll 8
            for (int k = l8; k < KK; k += 8) mx = fmaxf(mx, a_s[k * LS + t]);
            mx = fmaxf(mx, __shfl_xor_sync(0xffffffffu, mx, 1));
            mx = fmaxf(mx, __shfl_xor_sync(0xffffffffu, mx, 2));
            mx = fmaxf(mx, __shfl_xor_sync(0xffffffffu, mx, 4));
            float se = 0.f;
#pragma unroll 8
            for (int k = l8; k < KK; k += 8) {
                float e = expf(a_s[k * LS + t] - mx);
                a_s[k * LS + t] = e;
                se += e;
            }
            se += __shfl_xor_sync(0xffffffffu, se, 1);
            se += __shfl_xor_sync(0xffffffffu, se, 2);
            se += __shfl_xor_sync(0xffffffffu, se, 4);
            float inv = 1.0f / se;
#pragma unroll 8
            for (int k = l8; k < KK; k += 8) a_s[k * LS + t] *= inv;
        }
        __syncthreads();

        // VLAD accumulate: V[k][c] += a[k][t]*xn[t][c]
#pragma unroll 2
        for (int t = 0; t < TCH; ++t) {
            float a0 = a_s[(ty + 0)  * LS + t];
            float a1 = a_s[(ty + 16) * LS + t];
            float a2 = a_s[(ty + 32) * LS + t];
            float a3 = a_s[(ty + 48) * LS + t];
            asum[0] += a0; asum[1] += a1; asum[2] += a2; asum[3] += a3;
            u64 ap[4] = {pack2(a0, a0), pack2(a1, a1), pack2(a2, a2), pack2(a3, a3)};
            const float* xr = x_s + t * XS + 2 * tx;
#pragma unroll
            for (int j = 0; j < 8; j++) {
                u64 xv = *(const u64*)(xr + 32 * j);
#pragma unroll
                for (int q = 0; q < 4; q++) V2[q][j] = ffma2(ap[q], xv, V2[q][j]);
            }
        }
    }

    // store partials
    float* vp = g_vpart + ((size_t)(b * SLICES + sl) * KK) * CC;
#pragma unroll
    for (int q = 0; q < 4; q++) {
        int k = ty + 16 * q;
#pragma unroll
        for (int j = 0; j < 8; j++)
            *(u64*)(vp + k * CC + 2 * tx + 32 * j) = V2[q][j];
        if (tx == 0) g_apart[(b * SLICES + sl) * KK + k] = asum[q];
    }
}

// =====================================================================
// Kernel 2: reduce slices + centroid subtract + intra L2 norm
//           also emit per-row contribution to the global norm
// grid = (KK, BB), block = 256 (one thread per c)
// =====================================================================
__global__ __launch_bounds__(256) void k_reduce(const float* __restrict__ cent)
{
    const int k = blockIdx.x, b = blockIdx.y, c = threadIdx.x;
    float vs = 0.f;
#pragma unroll 4
    for (int s = 0; s < SLICES; ++s)
        vs += g_vpart[(((size_t)b * SLICES + s) * KK + k) * CC + c];
    float as = 0.f;
#pragma unroll 4
    for (int s = 0; s < SLICES; ++s)
        as += g_apart[(b * SLICES + s) * KK + k];
    float v = vs - as * cent[k * CC + c];

    __shared__ float red[8];
    float sq = v * v;
#pragma unroll
    for (int o = 16; o; o >>= 1) sq += __shfl_xor_sync(0xffffffffu, sq, o);
    if ((threadIdx.x & 31) == 0) red[threadIdx.x >> 5] = sq;
    __syncthreads();
    float tot = 0.f;
#pragma unroll
    for (int w = 0; w < 8; w++) tot += red[w];
    float inv = 1.0f / fmaxf(sqrtf(tot), 1e-12f);
    g_vladn[((size_t)b * KK + k) * CC + c] = v * inv;
    if (c == 0) g_rsq[b * KK + k] = tot * inv * inv;  // row norm^2 after intra-norm
}

// =====================================================================
// Kernel 3: hidden GEMM partials: [32,16384]x[16384,256], i-chunked
// grid = HCH (256), block = 512, 2 i-groups per CTA
// =====================================================================
__global__ __launch_bounds__(512, 2) void k_hidden(const float* __restrict__ hw)
{
    __shared__ float vs_s[BB * IC];   // 8 KB
    __shared__ float ps[BB * DD];     // 32 KB
    const int i0 = blockIdx.x * IC;
    const int tid = threadIdx.x;
    const int d = tid & 255, g = tid >> 8;

    for (int idx = tid; idx < BB * IC; idx += 512) {
        int bb = idx >> 6, ii = idx & 63;
        vs_s[idx] = g_vladn[(size_t)bb * (KK * CC) + i0 + ii];
    }
    __syncthreads();

    float P[BB];
#pragma unroll
    for (int bb = 0; bb < BB; bb++) P[bb] = 0.f;

    const float* wp = hw + (size_t)(i0 + g * 32) * DD + d;
#pragma unroll
    for (int i = 0; i < 32; ++i) {
        float w = wp[(size_t)i * DD];
        int ii = g * 32 + i;
#pragma unroll
        for (int bb = 0; bb < BB; bb++) P[bb] = fmaf(vs_s[bb * IC + ii], w, P[bb]);
    }

    if (g == 1) {
#pragma unroll
        for (int bb = 0; bb < BB; bb++) ps[bb * DD + d] = P[bb];
    }
    __syncthreads();
    if (g == 0) {
#pragma unroll
        for (int bb = 0; bb < BB; bb++)
            g_hpart[((size_t)blockIdx.x * BB + bb) * DD + d] = P[bb] + ps[bb * DD + d];
    }
}

// =====================================================================
// Kernel 4: reduce hidden partials, apply global inv-norm
// (warp 0 recomputes inv-norm from g_rsq in-register; k_gnorm removed)
// grid = (8, BB), block = 256
// =====================================================================
__global__ __launch_bounds__(256) void k_hreduce()
{
    __shared__ float red[8 * 33];
    const int b = blockIdx.y, dg = blockIdx.x;
    const int dl = threadIdx.x & 31, s8 = threadIdx.x >> 5;
    const int d = dg * 32 + dl;

    float inv = 0.f;
    if (s8 == 0) {  // warp 0: global norm from per-row contributions
        float s = g_rsq[b * KK + dl] + g_rsq[b * KK + 32 + dl];
#pragma unroll
        for (int o = 16; o; o >>= 1) s += __shfl_xor_sync(0xffffffffu, s, o);
        inv = 1.0f / fmaxf(sqrtf(s), 1e-12f);
    }

    float s = 0.f;
#pragma unroll 8
    for (int ch = s8; ch < HCH; ch += 8)
        s += g_hpart[((size_t)ch * BB + b) * DD + d];
    red[s8 * 33 + dl] = s;
    __syncthreads();
    if (s8 == 0) {
        float t = 0.f;
#pragma unroll
        for (int w = 0; w < 8; w++) t += red[w * 33 + dl];
        g_h[b * DD + d] = t * inv;
    }
}

// =====================================================================
// Kernel 5: BatchNorm over batch (training-mode, biased var)
// =====================================================================
__global__ __launch_bounds__(DD) void k_bn2(const float* __restrict__ gamma,
                                            const float* __restrict__ beta)
{
    const int d = threadIdx.x;
    float y[BB];
    float m = 0.f;
#pragma unroll
    for (int b = 0; b < BB; b++) { y[b] = g_h[b * DD + d]; m += y[b]; }
    m *= (1.0f / BB);
    float v = 0.f;
#pragma unroll
    for (int b = 0; b < BB; b++) { float dv = y[b] - m; v = fmaf(dv, dv, v); }
    v *= (1.0f / BB);
    float rs = 1.0f / sqrtf(v + 1e-5f);
    float ga = gamma[d], be = beta[d];
#pragma unroll
    for (int b = 0; b < BB; b++)
        g_y[b * DD + d] = ga * (y[b] - m) * rs + be;
}

// =====================================================================
// Kernel 6: gating GEMM z = y @ gating_w   ([32,256]x[256,256])
// =====================================================================
__global__ __launch_bounds__(DD) void k_gate(const float* __restrict__ gw)
{
    __shared__ float yb[DD];
    const int b = blockIdx.x, d = threadIdx.x;
    yb[d] = g_y[b * DD + d];
    __syncthreads();
    float z = 0.f;
#pragma unroll 4
    for (int dd = 0; dd < DD; ++dd) z = fmaf(yb[dd], gw[dd * DD + d], z);
    g_z[b * DD + d] = z;
}

// =====================================================================
// Kernel 7: gating BN + sigmoid + multiply -> output
// =====================================================================
__global__ __launch_bounds__(DD) void k_final(const float* __restrict__ gbn_g,
                                              const float* __restrict__ gbn_b,
                                              float* __restrict__ out)
{
    const int d = threadIdx.x;
    float z[BB];
    float m = 0.f;
#pragma unroll
    for (int b = 0; b < BB; b++) { z[b] = g_z[b * DD + d]; m += z[b]; }
    m *= (1.0f / BB);
    float v = 0.f;
#pragma unroll
    for (int b = 0; b < BB; b++) { float dv = z[b] - m; v = fmaf(dv, dv, v); }
    v *= (1.0f / BB);
    float rs = 1.0f / sqrtf(v + 1e-5f);
    float gg = gbn_g[d], gb = gbn_b[d];
#pragma unroll
    for (int b = 0; b < BB; b++) {
        float zn = gg * (z[b] - m) * rs + gb;
        float gate = 1.0f / (1.0f + expf(-zn));
        out[b * DD + d] = g_y[b * DD + d] * gate;
    }
}

// =====================================================================
extern "C" void kernel_launch(void* const* d_in, const int* in_sizes, int n_in,
                              void* d_out, int out_size)
{
    (void)in_sizes; (void)n_in; (void)out_size;
    const float* x      = (const float*)d_in[0];
    const float* conv_w = (const float*)d_in[1];
    const float* cent   = (const float*)d_in[2];
    const float* hw     = (const float*)d_in[3];
    const float* gw     = (const float*)d_in[4];
    const float* bn2g   = (const float*)d_in[5];
    const float* bn2b   = (const float*)d_in[6];
    const float* gbng   = (const float*)d_in[7];
    const float* gbnb   = (const float*)d_in[8];
    float* out = (float*)d_out;

    const size_t smem1 = (size_t)(TCH * XS + KK * LS) * sizeof(float);
    cudaFuncSetAttribute(k_vlad, cudaFuncAttributeMaxDynamicSharedMemorySize, (int)smem1);

    // 3x k_wt (idempotent): pads launch index so ncu capture hits k_vlad
    k_wt<<<(CC/2 * KK + 255) / 256, 256>>>(conv_w);
    k_wt<<<(CC/2 * KK + 255) / 256, 256>>>(conv_w);
    k_wt<<<(CC/2 * KK + 255) / 256, 256>>>(conv_w);
    k_vlad<<<dim3(SLICES, BB), 256, smem1>>>(x);
    k_reduce<<<dim3(KK, BB), 256>>>(cent);
    k_hidden<<<HCH, 512>>>(hw);
    k_hreduce<<<dim3(8, BB), 256>>>();
    k_bn2<<<1, DD>>>(bn2g, bn2b);
    k_gate<<<BB, DD>>>(gw);
    k_final<<<1, DD>>>(gbng, gbnb, out);
}

// round 7
// speedup vs baseline: 1.0764x; 1.0764x over previous
#include <cuda_runtime.h>
#include <math.h>

#define BB 32
#define NN 4096
#define CC 256
#define KK 64
#define DD 256
#define XS 260            /* x_s row stride (mult of 4) */
#define AS 33             /* a_s row stride */
#define NTA 128           /* kernel A: 32-token tiles per batch */
#define SLB 9             /* kernel B slices (chunk stride) */
#define NCHB 128          /* total 32-token chunks per batch */
#define HCH 256           /* hidden GEMM i-chunks */
#define IC 64             /* i per hidden chunk */

typedef unsigned long long u64;

// ---------------- device scratch (no allocations allowed) ----------------
__device__ __align__(16) float  g_a[(size_t)BB * NN * KK];               // 32 MB softmax assignments
__device__ __align__(16) float  g_inrm[BB * NN];                         // per-token inv norms
__device__ __align__(16) float  g_vpart[(size_t)BB * SLB * KK * CC];     // 18.9 MB
__device__ __align__(16) float  g_apart[BB * SLB * KK];
__device__ __align__(16) float  g_vladn[BB * KK * CC];
__device__ __align__(16) float  g_rsq[BB * KK];
__device__ __align__(16) float  g_hpart[HCH * BB * DD];                  // 8 MB
__device__ __align__(16) float  g_h[BB * DD];
__device__ __align__(16) float  g_y[BB * DD];
__device__ __align__(16) float  g_z[BB * DD];
__device__ __align__(16) float2 g_w2t[(CC/2) * KK];                      // 64 KB

// ---------------- f32x2 helpers (sm_100+ packed FFMA) ----------------
__device__ __forceinline__ u64 ffma2(u64 a, u64 b, u64 c) {
    u64 d;
    asm("fma.rn.f32x2 %0, %1, %2, %3;" : "=l"(d) : "l"(a), "l"(b), "l"(c));
    return d;
}
__device__ __forceinline__ u64 pack2(float lo, float hi) {
    u64 r;
    asm("mov.b64 %0, {%1, %2};" : "=l"(r) : "f"(lo), "f"(hi));
    return r;
}
__device__ __forceinline__ float2 unpack2(u64 v) {
    float2 f;
    asm("mov.b64 {%0, %1}, %2;" : "=f"(f.x), "=f"(f.y) : "l"(v));
    return f;
}

// =====================================================================
// Kernel 0: transpose conv_w -> w2t[c2][k]
// =====================================================================
__global__ __launch_bounds__(256) void k_wt(const float* __restrict__ conv_w)
{
    int idx = blockIdx.x * 256 + threadIdx.x;           // 8192 total
    if (idx < (CC/2) * KK) {
        int c2 = idx >> 6, k = idx & 63;
        g_w2t[idx] = make_float2(conv_w[k * CC + 2 * c2],
                                 conv_w[k * CC + 2 * c2 + 1]);
    }
}

// =====================================================================
// Kernel A: normalize + logits + softmax -> g_a, g_inrm
// grid = (NTA, BB), block = 128, ~5 CTAs/SM
// =====================================================================
__global__ __launch_bounds__(128) void k_logits(const float* __restrict__ x)
{
    __shared__ float x_s[32 * XS];     // 33.3 KB
    __shared__ float a_s[KK * AS];     // 8.4 KB

    const int b = blockIdx.y, tile = blockIdx.x;
    const int tid = threadIdx.x;
    const int tx = tid & 15, ty = tid >> 4;     // logits: k = tx+16q, t = ty+8r
    const int n0 = tile * 32;

    // stage 32 tokens x 256 c
    const float* xg = x + ((size_t)b * NN + n0) * CC;
    for (int i = tid; i < 32 * CC / 4; i += 128) {
        int t = i >> 6, c4 = i & 63;
        float4 v = *(const float4*)(xg + t * CC + 4 * c4);
        *(float4*)(x_s + t * XS + 4 * c4) = v;
    }
    __syncthreads();

    // per-token L2 normalize (4 threads per token), save inv-norm
    {
        int t = tid >> 2, l4 = tid & 3;
        float s = 0.f;
        for (int c = l4; c < CC; c += 4) { float v = x_s[t * XS + c]; s = fmaf(v, v, s); }
        s += __shfl_xor_sync(0xffffffffu, s, 1);
        s += __shfl_xor_sync(0xffffffffu, s, 2);
        float inv = 1.0f / fmaxf(sqrtf(s), 1e-12f);
        for (int c = l4; c < CC; c += 4) x_s[t * XS + c] *= inv;
        if (l4 == 0) g_inrm[b * NN + n0 + t] = inv;
    }
    __syncthreads();

    // logits: 4k x 4t register tile per thread
    {
        u64 acc[4][4];
#pragma unroll
        for (int q = 0; q < 4; q++)
#pragma unroll
            for (int r = 0; r < 4; r++) acc[q][r] = 0ULL;
        const float2* wp0 = g_w2t + tx;
        const float* xp0 = x_s + ty * XS;
#pragma unroll 4
        for (int c2 = 0; c2 < CC / 2; ++c2) {
            u64 w2[4], x2[4];
#pragma unroll
            for (int q = 0; q < 4; q++)
                w2[q] = *(const u64*)(wp0 + c2 * KK + 16 * q);
#pragma unroll
            for (int r = 0; r < 4; r++)
                x2[r] = *(const u64*)(xp0 + r * 8 * XS + 2 * c2);
#pragma unroll
            for (int q = 0; q < 4; q++)
#pragma unroll
                for (int r = 0; r < 4; r++)
                    acc[q][r] = ffma2(w2[q], x2[r], acc[q][r]);
        }
#pragma unroll
        for (int q = 0; q < 4; q++)
#pragma unroll
            for (int r = 0; r < 4; r++) {
                float2 f = unpack2(acc[q][r]);
                a_s[(tx + 16 * q) * AS + (ty + 8 * r)] = f.x + f.y;
            }
    }
    __syncthreads();

    // softmax over k per token (4 threads per token)
    {
        int t = tid >> 2, l4 = tid & 3;
        float mx = -1e30f;
        for (int k = l4; k < KK; k += 4) mx = fmaxf(mx, a_s[k * AS + t]);
        mx = fmaxf(mx, __shfl_xor_sync(0xffffffffu, mx, 1));
        mx = fmaxf(mx, __shfl_xor_sync(0xffffffffu, mx, 2));
        float se = 0.f;
        for (int k = l4; k < KK; k += 4) {
            float e = expf(a_s[k * AS + t] - mx);
            a_s[k * AS + t] = e;
            se += e;
        }
        se += __shfl_xor_sync(0xffffffffu, se, 1);
        se += __shfl_xor_sync(0xffffffffu, se, 2);
        float inv = 1.0f / se;
        for (int k = l4; k < KK; k += 4) a_s[k * AS + t] *= inv;
    }
    __syncthreads();

    // write a tile packed [k][32t]
    float* ag = g_a + ((size_t)(b * NTA + tile)) * (KK * 32);
    for (int i = tid; i < KK * 32; i += 128) {
        int k = i >> 5, t = i & 31;
        ag[i] = a_s[k * AS + t];
    }
}

// =====================================================================
// Kernel B: VLAD partial accumulate  V[k][c] += a[k][t]*xn[t][c]
// grid = (SLB, BB) = 288 CTAs, block = 256, 2 CTAs/SM, chunk-strided
// =====================================================================
__global__ __launch_bounds__(256, 2) void k_vlad(const float* __restrict__ x)
{
    __shared__ float x_s[32 * XS];     // 33.3 KB
    __shared__ float a_s[KK * AS];     // 8.4 KB

    const int b = blockIdx.y, sl = blockIdx.x;
    const int tid = threadIdx.x;
    const int tx = tid & 15, ty = tid >> 4;

    u64 V2[4][8];
#pragma unroll
    for (int q = 0; q < 4; q++)
#pragma unroll
        for (int j = 0; j < 8; j++) V2[q][j] = 0ULL;
    float asum[4] = {0.f, 0.f, 0.f, 0.f};

    for (int ch = sl; ch < NCHB; ch += SLB) {
        __syncthreads();
        const int n0 = ch * 32;
        const float* xg = x + ((size_t)b * NN + n0) * CC;
        const float* ing = g_inrm + b * NN + n0;
        for (int i = tid; i < 32 * CC / 4; i += 256) {
            int t = i >> 6, c4 = i & 63;
            float inv = ing[t];
            float4 v = *(const float4*)(xg + t * CC + 4 * c4);
            v.x *= inv; v.y *= inv; v.z *= inv; v.w *= inv;
            *(float4*)(x_s + t * XS + 4 * c4) = v;
        }
        const float* ag = g_a + ((size_t)(b * NTA + ch)) * (KK * 32);
        for (int i = tid; i < KK * 32; i += 256) {
            int k = i >> 5, t = i & 31;
            a_s[k * AS + t] = ag[i];
        }
        __syncthreads();

        // VLAD accumulate
#pragma unroll 2
        for (int t = 0; t < 32; ++t) {
            float a0 = a_s[(ty + 0)  * AS + t];
            float a1 = a_s[(ty + 16) * AS + t];
            float a2 = a_s[(ty + 32) * AS + t];
            float a3 = a_s[(ty + 48) * AS + t];
            asum[0] += a0; asum[1] += a1; asum[2] += a2; asum[3] += a3;
            u64 ap[4] = {pack2(a0, a0), pack2(a1, a1), pack2(a2, a2), pack2(a3, a3)};
            const float* xr = x_s + t * XS + 2 * tx;
#pragma unroll
            for (int j = 0; j < 8; j++) {
                u64 xv = *(const u64*)(xr + 32 * j);
#pragma unroll
                for (int q = 0; q < 4; q++) V2[q][j] = ffma2(ap[q], xv, V2[q][j]);
            }
        }
    }

    // store partials
    float* vp = g_vpart + ((size_t)(b * SLB + sl) * KK) * CC;
#pragma unroll
    for (int q = 0; q < 4; q++) {
        int k = ty + 16 * q;
#pragma unroll
        for (int j = 0; j < 8; j++)
            *(u64*)(vp + k * CC + 2 * tx + 32 * j) = V2[q][j];
        if (tx == 0) g_apart[(b * SLB + sl) * KK + k] = asum[q];
    }
}

// =====================================================================
// Kernel 2: reduce slices + centroid subtract + intra L2 norm
// grid = (KK, BB), block = 256
// =====================================================================
__global__ __launch_bounds__(256) void k_reduce(const float* __restrict__ cent)
{
    const int k = blockIdx.x, b = blockIdx.y, c = threadIdx.x;
    float vs = 0.f;
#pragma unroll 3
    for (int s = 0; s < SLB; ++s)
        vs += g_vpart[(((size_t)b * SLB + s) * KK + k) * CC + c];
    float as = 0.f;
#pragma unroll 3
    for (int s = 0; s < SLB; ++s)
        as += g_apart[(b * SLB + s) * KK + k];
    float v = vs - as * cent[k * CC + c];

    __shared__ float red[8];
    float sq = v * v;
#pragma unroll
    for (int o = 16; o; o >>= 1) sq += __shfl_xor_sync(0xffffffffu, sq, o);
    if ((threadIdx.x & 31) == 0) red[threadIdx.x >> 5] = sq;
    __syncthreads();
    float tot = 0.f;
#pragma unroll
    for (int w = 0; w < 8; w++) tot += red[w];
    float inv = 1.0f / fmaxf(sqrtf(tot), 1e-12f);
    g_vladn[((size_t)b * KK + k) * CC + c] = v * inv;
    if (c == 0) g_rsq[b * KK + k] = tot * inv * inv;
}

// =====================================================================
// Kernel 3: hidden GEMM partials: [32,16384]x[16384,256], i-chunked
// grid = HCH (256), block = 512, 2 i-groups per CTA
// =====================================================================
__global__ __launch_bounds__(512, 2) void k_hidden(const float* __restrict__ hw)
{
    __shared__ float vs_s[BB * IC];   // 8 KB
    __shared__ float ps[BB * DD];     // 32 KB
    const int i0 = blockIdx.x * IC;
    const int tid = threadIdx.x;
    const int d = tid & 255, g = tid >> 8;

    for (int idx = tid; idx < BB * IC; idx += 512) {
        int bb = idx >> 6, ii = idx & 63;
        vs_s[idx] = g_vladn[(size_t)bb * (KK * CC) + i0 + ii];
    }
    __syncthreads();

    float P[BB];
#pragma unroll
    for (int bb = 0; bb < BB; bb++) P[bb] = 0.f;

    const float* wp = hw + (size_t)(i0 + g * 32) * DD + d;
#pragma unroll
    for (int i = 0; i < 32; ++i) {
        float w = wp[(size_t)i * DD];
        int ii = g * 32 + i;
#pragma unroll
        for (int bb = 0; bb < BB; bb++) P[bb] = fmaf(vs_s[bb * IC + ii], w, P[bb]);
    }

    if (g == 1) {
#pragma unroll
        for (int bb = 0; bb < BB; bb++) ps[bb * DD + d] = P[bb];
    }
    __syncthreads();
    if (g == 0) {
#pragma unroll
        for (int bb = 0; bb < BB; bb++)
            g_hpart[((size_t)blockIdx.x * BB + bb) * DD + d] = P[bb] + ps[bb * DD + d];
    }
}

// =====================================================================
// Kernel 4: reduce hidden partials, apply global inv-norm
// grid = (8, BB), block = 256
// =====================================================================
__global__ __launch_bounds__(256) void k_hreduce()
{
    __shared__ float red[8 * 33];
    const int b = blockIdx.y, dg = blockIdx.x;
    const int dl = threadIdx.x & 31, s8 = threadIdx.x >> 5;
    const int d = dg * 32 + dl;

    float inv = 0.f;
    if (s8 == 0) {
        float s = g_rsq[b * KK + dl] + g_rsq[b * KK + 32 + dl];
#pragma unroll
        for (int o = 16; o; o >>= 1) s += __shfl_xor_sync(0xffffffffu, s, o);
        inv = 1.0f / fmaxf(sqrtf(s), 1e-12f);
    }

    float s = 0.f;
#pragma unroll 8
    for (int ch = s8; ch < HCH; ch += 8)
        s += g_hpart[((size_t)ch * BB + b) * DD + d];
    red[s8 * 33 + dl] = s;
    __syncthreads();
    if (s8 == 0) {
        float t = 0.f;
#pragma unroll
        for (int w = 0; w < 8; w++) t += red[w * 33 + dl];
        g_h[b * DD + d] = t * inv;
    }
}

// =====================================================================
// Kernel 5: BatchNorm over batch (training-mode, biased var)
// =====================================================================
__global__ __launch_bounds__(DD) void k_bn2(const float* __restrict__ gamma,
                                            const float* __restrict__ beta)
{
    const int d = threadIdx.x;
    float y[BB];
    float m = 0.f;
#pragma unroll
    for (int b = 0; b < BB; b++) { y[b] = g_h[b * DD + d]; m += y[b]; }
    m *= (1.0f / BB);
    float v = 0.f;
#pragma unroll
    for (int b = 0; b < BB; b++) { float dv = y[b] - m; v = fmaf(dv, dv, v); }
    v *= (1.0f / BB);
    float rs = 1.0f / sqrtf(v + 1e-5f);
    float ga = gamma[d], be = beta[d];
#pragma unroll
    for (int b = 0; b < BB; b++)
        g_y[b * DD + d] = ga * (y[b] - m) * rs + be;
}

// =====================================================================
// Kernel 6: gating GEMM z = y @ gating_w   ([32,256]x[256,256])
// =====================================================================
__global__ __launch_bounds__(DD) void k_gate(const float* __restrict__ gw)
{
    __shared__ float yb[DD];
    const int b = blockIdx.x, d = threadIdx.x;
    yb[d] = g_y[b * DD + d];
    __syncthreads();
    float z = 0.f;
#pragma unroll 4
    for (int dd = 0; dd < DD; ++dd) z = fmaf(yb[dd], gw[dd * DD + d], z);
    g_z[b * DD + d] = z;
}

// =====================================================================
// Kernel 7: gating BN + sigmoid + multiply -> output
// =====================================================================
__global__ __launch_bounds__(DD) void k_final(const float* __restrict__ gbn_g,
                                              const float* __restrict__ gbn_b,
                                              float* __restrict__ out)
{
    const int d = threadIdx.x;
    float z[BB];
    float m = 0.f;
#pragma unroll
    for (int b = 0; b < BB; b++) { z[b] = g_z[b * DD + d]; m += z[b]; }
    m *= (1.0f / BB);
    float v = 0.f;
#pragma unroll
    for (int b = 0; b < BB; b++) { float dv = z[b] - m; v = fmaf(dv, dv, v); }
    v *= (1.0f / BB);
    float rs = 1.0f / sqrtf(v + 1e-5f);
    float gg = gbn_g[d], gb = gbn_b[d];
#pragma unroll
    for (int b = 0; b < BB; b++) {
        float zn = gg * (z[b] - m) * rs + gb;
        float gate = 1.0f / (1.0f + expf(-zn));
        out[b * DD + d] = g_y[b * DD + d] * gate;
    }
}

// =====================================================================
extern "C" void kernel_launch(void* const* d_in, const int* in_sizes, int n_in,
                              void* d_out, int out_size)
{
    (void)in_sizes; (void)n_in; (void)out_size;
    const float* x      = (const float*)d_in[0];
    const float* conv_w = (const float*)d_in[1];
    const float* cent   = (const float*)d_in[2];
    const float* hw     = (const float*)d_in[3];
    const float* gw     = (const float*)d_in[4];
    const float* bn2g   = (const float*)d_in[5];
    const float* bn2b   = (const float*)d_in[6];
    const float* gbng   = (const float*)d_in[7];
    const float* gbnb   = (const float*)d_in[8];
    float* out = (float*)d_out;

    // 2x k_wt (idempotent; 2nd pads launch index so ncu capture hits k_vlad)
    k_wt<<<(CC/2 * KK + 255) / 256, 256>>>(conv_w);
    k_wt<<<(CC/2 * KK + 255) / 256, 256>>>(conv_w);
    k_logits<<<dim3(NTA, BB), 128>>>(x);
    k_vlad<<<dim3(SLB, BB), 256>>>(x);
    k_reduce<<<dim3(KK, BB), 256>>>(cent);
    k_hidden<<<HCH, 512>>>(hw);
    k_hreduce<<<dim3(8, BB), 256>>>();
    k_bn2<<<1, DD>>>(bn2g, bn2b);
    k_gate<<<BB, DD>>>(gw);
    k_final<<<1, DD>>>(gbng, gbnb, out);
}

// round 9
// speedup vs baseline: 1.3367x; 1.2418x over previous
#include <cuda_runtime.h>
#include <cuda_bf16.h>
#include <math.h>

#define BB 32
#define NN 4096
#define CC 256
#define KK 64
#define DD 256
#define XS 260            /* k_vlad x_s row stride */
#define AS 33             /* k_vlad a_s row stride */
#define NTA 128           /* 32-token a-tiles per batch (g_a layout) */
#define SLB 9             /* k_vlad slices */
#define NCHB 128          /* 32-token chunks per batch */
#define HCH 256
#define IC 64
#define NT128 (NN/128)    /* 32 token-tiles of 128 for k_logits */

typedef unsigned long long u64;

// ---------------- device scratch ----------------
__device__ __align__(16) float  g_a[(size_t)BB * NN * KK];               // 32 MB
__device__ __align__(16) float  g_inrm[BB * NN];
__device__ __align__(16) float  g_vpart[(size_t)BB * SLB * KK * CC];
__device__ __align__(16) float  g_apart[BB * SLB * KK];
__device__ __align__(16) float  g_vladn[BB * KK * CC];
__device__ __align__(16) float  g_rsq[BB * KK];
__device__ __align__(16) float  g_hpart[HCH * BB * DD];
__device__ __align__(16) float  g_h[BB * DD];
__device__ __align__(16) float  g_y[BB * DD];
__device__ __align__(16) float  g_z[BB * DD];
__device__ __align__(16) __nv_bfloat16 g_wh[4 * 64 * 64];  // w hi, [kc][c][n] swizzled
__device__ __align__(16) __nv_bfloat16 g_wl[4 * 64 * 64];  // w lo

// ---------------- f32x2 helpers ----------------
__device__ __forceinline__ u64 ffma2(u64 a, u64 b, u64 c) {
    u64 d;
    asm("fma.rn.f32x2 %0, %1, %2, %3;" : "=l"(d) : "l"(a), "l"(b), "l"(c));
    return d;
}
__device__ __forceinline__ u64 pack2(float lo, float hi) {
    u64 r;
    asm("mov.b64 %0, {%1, %2};" : "=l"(r) : "f"(lo), "f"(hi));
    return r;
}

// ---------------- mma.sync / ldmatrix helpers (base sm_103 features) ----
__device__ __forceinline__ unsigned smem_u32(const void* p) {
    unsigned a;
    asm("{ .reg .u64 t; cvta.to.shared.u64 t, %1; cvt.u32.u64 %0, t; }" : "=r"(a) : "l"(p));
    return a;
}
#define SWZ(off) ((off) ^ (((off) >> 3) & 0x70))

__device__ __forceinline__ void ldsm4(unsigned* r, unsigned a) {
    asm volatile("ldmatrix.sync.aligned.m8n8.x4.shared.b16 {%0,%1,%2,%3}, [%4];"
        : "=r"(r[0]), "=r"(r[1]), "=r"(r[2]), "=r"(r[3]) : "r"(a));
}
__device__ __forceinline__ void ldsm4t(unsigned* r, unsigned a) {
    asm volatile("ldmatrix.sync.aligned.m8n8.x4.trans.shared.b16 {%0,%1,%2,%3}, [%4];"
        : "=r"(r[0]), "=r"(r[1]), "=r"(r[2]), "=r"(r[3]) : "r"(a));
}
__device__ __forceinline__ void mma16816(float* c, const unsigned* a, const unsigned* b) {
    asm volatile("mma.sync.aligned.m16n8k16.row.col.f32.bf16.bf16.f32 "
        "{%0,%1,%2,%3}, {%4,%5,%6,%7}, {%8,%9}, {%0,%1,%2,%3};"
        : "+f"(c[0]), "+f"(c[1]), "+f"(c[2]), "+f"(c[3])
        : "r"(a[0]), "r"(a[1]), "r"(a[2]), "r"(a[3]), "r"(b[0]), "r"(b[1]));
}

// smem byte offsets for k_logits
#define SM_INRM 0
#define SM_XHI  1024          /* 128t x 64c bf16, 128B rows, SW128  (16 KB) */
#define SM_XLO  17408
#define SM_WHI  33792         /* 64c x 64n bf16, 128B rows, SW128   (8 KB)  */
#define SM_WLO  41984
#define SM_TOTAL 50176

// =====================================================================
// Kernel W: split conv_w into bf16 hi/lo, layout [kc][c(64)][n=k], SW128
// =====================================================================
__global__ __launch_bounds__(256) void k_wtb(const float* __restrict__ conv_w)
{
    int idx = blockIdx.x * 256 + threadIdx.x;   // 16384
    if (idx < KK * CC) {
        int k = idx >> 8, c = idx & 255;
        int kc = c >> 6, cc = c & 63;
        float v = conv_w[k * CC + c];
        __nv_bfloat16 h = __float2bfloat16(v);
        __nv_bfloat16 l = __float2bfloat16(v - __bfloat162float(h));
        unsigned off = (unsigned)(cc * 128 + k * 2);
        unsigned sw = SWZ(off);
        *(__nv_bfloat16*)((char*)g_wh + kc * 8192 + sw) = h;
        *(__nv_bfloat16*)((char*)g_wl + kc * 8192 + sw) = l;
    }
}

// =====================================================================
// Kernel A: normalize + logits (mma.sync bf16-split) + softmax -> g_a
// grid = (NT128, BB), block = 128 (4 warps), 4 CTAs/SM
// warp w owns token rows [w*32, w*32+32); acc = m32 x n64 fp32 fragments
// =====================================================================
__global__ __launch_bounds__(128, 4) void k_logits(const float* __restrict__ x)
{
    extern __shared__ char smem[];
    const unsigned sb = smem_u32(smem);
    const int tid = threadIdx.x, wid = tid >> 5, lane = tid & 31;
    const int b = blockIdx.y, tile = blockIdx.x;
    const int n0 = tile * 128;
    float* inrm_s = (float*)(smem + SM_INRM);

    // --- norm pass: 4 lanes per token ---
    const float4* xg4 = (const float4*)(x + ((size_t)b * NN + n0) * CC);
#pragma unroll
    for (int rep = 0; rep < 4; ++rep) {
        int t = rep * 32 + (tid >> 2), l4 = tid & 3;
        float s = 0.f;
#pragma unroll
        for (int i = 0; i < 16; ++i) {
            float4 v = xg4[t * 64 + l4 + 4 * i];
            s = fmaf(v.x, v.x, s); s = fmaf(v.y, v.y, s);
            s = fmaf(v.z, v.z, s); s = fmaf(v.w, v.w, s);
        }
        s += __shfl_xor_sync(0xffffffffu, s, 1);
        s += __shfl_xor_sync(0xffffffffu, s, 2);
        float inv = 1.0f / fmaxf(sqrtf(s), 1e-12f);
        if (l4 == 0) { inrm_s[t] = inv; g_inrm[b * NN + n0 + t] = inv; }
    }
    __syncthreads();

    float acc[2][8][4];
#pragma unroll
    for (int mt = 0; mt < 2; ++mt)
#pragma unroll
        for (int nt = 0; nt < 8; ++nt)
#pragma unroll
            for (int e = 0; e < 4; ++e) acc[mt][nt][e] = 0.f;

    // --- K-chunk loop ---
#pragma unroll 1
    for (int kc = 0; kc < 4; ++kc) {
        // copy pre-swizzled w chunk (hi+lo, 8 KB each)
        const uint4* gwh = (const uint4*)((const char*)g_wh + kc * 8192);
        const uint4* gwl = (const uint4*)((const char*)g_wl + kc * 8192);
#pragma unroll
        for (int i = 0; i < 4; ++i) {
            ((uint4*)(smem + SM_WHI))[tid + 128 * i] = gwh[tid + 128 * i];
            ((uint4*)(smem + SM_WLO))[tid + 128 * i] = gwl[tid + 128 * i];
        }
        // convert x chunk -> bf16 hi/lo, swizzled
#pragma unroll
        for (int r = 0; r < 8; ++r) {
            int idx = r * 128 + tid;
            int t = idx >> 3, u = idx & 7;
            float inv = inrm_s[t];
            float4 v0 = xg4[t * 64 + kc * 16 + u * 2];
            float4 v1 = xg4[t * 64 + kc * 16 + u * 2 + 1];
            float f[8] = {v0.x*inv, v0.y*inv, v0.z*inv, v0.w*inv,
                          v1.x*inv, v1.y*inv, v1.z*inv, v1.w*inv};
            unsigned hw_[4], lw_[4];
#pragma unroll
            for (int j = 0; j < 4; ++j) {
                __nv_bfloat16 h0 = __float2bfloat16(f[2*j]);
                __nv_bfloat16 h1 = __float2bfloat16(f[2*j+1]);
                __nv_bfloat16 l0 = __float2bfloat16(f[2*j]   - __bfloat162float(h0));
                __nv_bfloat16 l1 = __float2bfloat16(f[2*j+1] - __bfloat162float(h1));
                hw_[j] = ((unsigned)*(unsigned short*)&h1 << 16) | *(unsigned short*)&h0;
                lw_[j] = ((unsigned)*(unsigned short*)&l1 << 16) | *(unsigned short*)&l0;
            }
            unsigned sw = SWZ((unsigned)(t * 128 + u * 16));
            *(uint4*)(smem + SM_XHI + sw) = make_uint4(hw_[0], hw_[1], hw_[2], hw_[3]);
            *(uint4*)(smem + SM_XLO + sw) = make_uint4(lw_[0], lw_[1], lw_[2], lw_[3]);
        }
        __syncthreads();

        // --- MMA: 4 k16-steps ---
#pragma unroll
        for (int ks = 0; ks < 4; ++ks) {
            unsigned ahi[2][4], alo[2][4];
#pragma unroll
            for (int mt = 0; mt < 2; ++mt) {
                int row = wid * 32 + mt * 16 + (lane & 15);
                unsigned cb = (unsigned)(ks * 32 + ((lane >> 4) * 16));
                unsigned off = SWZ((unsigned)(row * 128) + cb);
                ldsm4(ahi[mt], sb + SM_XHI + off);
                ldsm4(alo[mt], sb + SM_XLO + off);
            }
            int krow = ks * 16 + (lane & 7) + 8 * ((lane >> 3) & 1);
            unsigned cb2 = (unsigned)((lane >> 4) * 16);
#pragma unroll
            for (int np = 0; np < 4; ++np) {
                unsigned bh[4], bl[4];
                unsigned off = SWZ((unsigned)(krow * 128) + (unsigned)(np * 32) + cb2);
                ldsm4t(bh, sb + SM_WHI + off);
                ldsm4t(bl, sb + SM_WLO + off);
#pragma unroll
                for (int mt = 0; mt < 2; ++mt) {
                    mma16816(acc[mt][2*np],     ahi[mt], bh);
                    mma16816(acc[mt][2*np],     ahi[mt], bl);
                    mma16816(acc[mt][2*np],     alo[mt], bh);
                    mma16816(acc[mt][2*np+1],   ahi[mt], bh + 2);
                    mma16816(acc[mt][2*np+1],   ahi[mt], bl + 2);
                    mma16816(acc[mt][2*np+1],   alo[mt], bh + 2);
                }
            }
        }
        __syncthreads();
    }

    // --- epilogue: softmax per token (group-of-4 owns a row), stage a_s ---
    const int g = lane >> 2, tg = lane & 3;
    float* a_s = (float*)(smem + SM_XHI);   // 64 x (130) floats, reuses x/w space
#pragma unroll
    for (int mt = 0; mt < 2; ++mt) {
#pragma unroll
        for (int i = 0; i < 2; ++i) {
            float mx = -1e30f;
#pragma unroll
            for (int nt = 0; nt < 8; ++nt) {
                mx = fmaxf(mx, acc[mt][nt][2*i]);
                mx = fmaxf(mx, acc[mt][nt][2*i+1]);
            }
            mx = fmaxf(mx, __shfl_xor_sync(0xffffffffu, mx, 1));
            mx = fmaxf(mx, __shfl_xor_sync(0xffffffffu, mx, 2));
            float se = 0.f;
#pragma unroll
            for (int nt = 0; nt < 8; ++nt) {
                acc[mt][nt][2*i]   = expf(acc[mt][nt][2*i]   - mx);
                acc[mt][nt][2*i+1] = expf(acc[mt][nt][2*i+1] - mx);
                se += acc[mt][nt][2*i] + acc[mt][nt][2*i+1];
            }
            se += __shfl_xor_sync(0xffffffffu, se, 1);
            se += __shfl_xor_sync(0xffffffffu, se, 2);
            float inv = 1.0f / se;
            int t = wid * 32 + mt * 16 + 8 * i + g;
#pragma unroll
            for (int nt = 0; nt < 8; ++nt) {
                a_s[(nt*8 + 2*tg    ) * 130 + t] = acc[mt][nt][2*i]   * inv;
                a_s[(nt*8 + 2*tg + 1) * 130 + t] = acc[mt][nt][2*i+1] * inv;
            }
        }
    }
    __syncthreads();

    // coalesced copy-out: g_a tiles of 32 tokens, [k][t32]
    float* ag = g_a + (size_t)(b * NTA + tile * 4) * (KK * 32);
    for (int i = tid; i < KK * 128; i += 128) {
        int k = i >> 7, t = i & 127;
        ag[(size_t)(t >> 5) * (KK * 32) + k * 32 + (t & 31)] = a_s[k * 130 + t];
    }
}

// =====================================================================
// Kernel B: VLAD partial accumulate (unchanged, 134 us)
// =====================================================================
__global__ __launch_bounds__(256, 2) void k_vlad(const float* __restrict__ x)
{
    __shared__ float x_s[32 * XS];
    __shared__ float a_s[KK * AS];

    const int b = blockIdx.y, sl = blockIdx.x;
    const int tid = threadIdx.x;
    const int tx = tid & 15, ty = tid >> 4;

    u64 V2[4][8];
#pragma unroll
    for (int q = 0; q < 4; q++)
#pragma unroll
        for (int j = 0; j < 8; j++) V2[q][j] = 0ULL;
    float asum[4] = {0.f, 0.f, 0.f, 0.f};

    for (int ch = sl; ch < NCHB; ch += SLB) {
        __syncthreads();
        const int n0 = ch * 32;
        const float* xg = x + ((size_t)b * NN + n0) * CC;
        const float* ing = g_inrm + b * NN + n0;
        for (int i = tid; i < 32 * CC / 4; i += 256) {
            int t = i >> 6, c4 = i & 63;
            float inv = ing[t];
            float4 v = *(const float4*)(xg + t * CC + 4 * c4);
            v.x *= inv; v.y *= inv; v.z *= inv; v.w *= inv;
            *(float4*)(x_s + t * XS + 4 * c4) = v;
        }
        const float* ag = g_a + ((size_t)(b * NTA + ch)) * (KK * 32);
        for (int i = tid; i < KK * 32; i += 256) {
            int k = i >> 5, t = i & 31;
            a_s[k * AS + t] = ag[i];
        }
        __syncthreads();

#pragma unroll 2
        for (int t = 0; t < 32; ++t) {
            float a0 = a_s[(ty + 0)  * AS + t];
            float a1 = a_s[(ty + 16) * AS + t];
            float a2 = a_s[(ty + 32) * AS + t];
            float a3 = a_s[(ty + 48) * AS + t];
            asum[0] += a0; asum[1] += a1; asum[2] += a2; asum[3] += a3;
            u64 ap[4] = {pack2(a0, a0), pack2(a1, a1), pack2(a2, a2), pack2(a3, a3)};
            const float* xr = x_s + t * XS + 2 * tx;
#pragma unroll
            for (int j = 0; j < 8; j++) {
                u64 xv = *(const u64*)(xr + 32 * j);
#pragma unroll
                for (int q = 0; q < 4; q++) V2[q][j] = ffma2(ap[q], xv, V2[q][j]);
            }
        }
    }

    float* vp = g_vpart + ((size_t)(b * SLB + sl) * KK) * CC;
#pragma unroll
    for (int q = 0; q < 4; q++) {
        int k = ty + 16 * q;
#pragma unroll
        for (int j = 0; j < 8; j++)
            *(u64*)(vp + k * CC + 2 * tx + 32 * j) = V2[q][j];
        if (tx == 0) g_apart[(b * SLB + sl) * KK + k] = asum[q];
    }
}

// =====================================================================
// Kernel 2: reduce slices + centroid subtract + intra L2 norm
// =====================================================================
__global__ __launch_bounds__(256) void k_reduce(const float* __restrict__ cent)
{
    const int k = blockIdx.x, b = blockIdx.y, c = threadIdx.x;
    float vs = 0.f;
#pragma unroll 3
    for (int s = 0; s < SLB; ++s)
        vs += g_vpart[(((size_t)b * SLB + s) * KK + k) * CC + c];
    float as = 0.f;
#pragma unroll 3
    for (int s = 0; s < SLB; ++s)
        as += g_apart[(b * SLB + s) * KK + k];
    float v = vs - as * cent[k * CC + c];

    __shared__ float red[8];
    float sq = v * v;
#pragma unroll
    for (int o = 16; o; o >>= 1) sq += __shfl_xor_sync(0xffffffffu, sq, o);
    if ((threadIdx.x & 31) == 0) red[threadIdx.x >> 5] = sq;
    __syncthreads();
    float tot = 0.f;
#pragma unroll
    for (int w = 0; w < 8; w++) tot += red[w];
    float inv = 1.0f / fmaxf(sqrtf(tot), 1e-12f);
    g_vladn[((size_t)b * KK + k) * CC + c] = v * inv;
    if (c == 0) g_rsq[b * KK + k] = tot * inv * inv;
}

// =====================================================================
// Kernel 3: hidden GEMM partials
// =====================================================================
__global__ __launch_bounds__(512, 2) void k_hidden(const float* __restrict__ hw)
{
    __shared__ float vs_s[BB * IC];
    __shared__ float ps[BB * DD];
    const int i0 = blockIdx.x * IC;
    const int tid = threadIdx.x;
    const int d = tid & 255, g = tid >> 8;

    for (int idx = tid; idx < BB * IC; idx += 512) {
        int bb = idx >> 6, ii = idx & 63;
        vs_s[idx] = g_vladn[(size_t)bb * (KK * CC) + i0 + ii];
    }
    __syncthreads();

    float P[BB];
#pragma unroll
    for (int bb = 0; bb < BB; bb++) P[bb] = 0.f;

    const float* wp = hw + (size_t)(i0 + g * 32) * DD + d;
#pragma unroll
    for (int i = 0; i < 32; ++i) {
        float w = wp[(size_t)i * DD];
        int ii = g * 32 + i;
#pragma unroll
        for (int bb = 0; bb < BB; bb++) P[bb] = fmaf(vs_s[bb * IC + ii], w, P[bb]);
    }

    if (g == 1) {
#pragma unroll
        for (int bb = 0; bb < BB; bb++) ps[bb * DD + d] = P[bb];
    }
    __syncthreads();
    if (g == 0) {
#pragma unroll
        for (int bb = 0; bb < BB; bb++)
            g_hpart[((size_t)blockIdx.x * BB + bb) * DD + d] = P[bb] + ps[bb * DD + d];
    }
}

// =====================================================================
// Kernel 4: reduce hidden partials + global inv-norm
// =====================================================================
__global__ __launch_bounds__(256) void k_hreduce()
{
    __shared__ float red[8 * 33];
    const int b = blockIdx.y, dg = blockIdx.x;
    const int dl = threadIdx.x & 31, s8 = threadIdx.x >> 5;
    const int d = dg * 32 + dl;

    float inv = 0.f;
    if (s8 == 0) {
        float s = g_rsq[b * KK + dl] + g_rsq[b * KK + 32 + dl];
#pragma unroll
        for (int o = 16; o; o >>= 1) s += __shfl_xor_sync(0xffffffffu, s, o);
        inv = 1.0f / fmaxf(sqrtf(s), 1e-12f);
    }

    float s = 0.f;
#pragma unroll 8
    for (int ch = s8; ch < HCH; ch += 8)
        s += g_hpart[((size_t)ch * BB + b) * DD + d];
    red[s8 * 33 + dl] = s;
    __syncthreads();
    if (s8 == 0) {
        float t = 0.f;
#pragma unroll
        for (int w = 0; w < 8; w++) t += red[w * 33 + dl];
        g_h[b * DD + d] = t * inv;
    }
}

// =====================================================================
// Kernel 5/6/7: BN2, gating GEMM, final
// =====================================================================
__global__ __launch_bounds__(DD) void k_bn2(const float* __restrict__ gamma,
                                            const float* __restrict__ beta)
{
    const int d = threadIdx.x;
    float y[BB];
    float m = 0.f;
#pragma unroll
    for (int b = 0; b < BB; b++) { y[b] = g_h[b * DD + d]; m += y[b]; }
    m *= (1.0f / BB);
    float v = 0.f;
#pragma unroll
    for (int b = 0; b < BB; b++) { float dv = y[b] - m; v = fmaf(dv, dv, v); }
    v *= (1.0f / BB);
    float rs = 1.0f / sqrtf(v + 1e-5f);
    float ga = gamma[d], be = beta[d];
#pragma unroll
    for (int b = 0; b < BB; b++)
        g_y[b * DD + d] = ga * (y[b] - m) * rs + be;
}

__global__ __launch_bounds__(DD) void k_gate(const float* __restrict__ gw)
{
    __shared__ float yb[DD];
    const int b = blockIdx.x, d = threadIdx.x;
    yb[d] = g_y[b * DD + d];
    __syncthreads();
    float z = 0.f;
#pragma unroll 4
    for (int dd = 0; dd < DD; ++dd) z = fmaf(yb[dd], gw[dd * DD + d], z);
    g_z[b * DD + d] = z;
}

__global__ __launch_bounds__(DD) void k_final(const float* __restrict__ gbn_g,
                                              const float* __restrict__ gbn_b,
                                              float* __restrict__ out)
{
    const int d = threadIdx.x;
    float z[BB];
    float m = 0.f;
#pragma unroll
    for (int b = 0; b < BB; b++) { z[b] = g_z[b * DD + d]; m += z[b]; }
    m *= (1.0f / BB);
    float v = 0.f;
#pragma unroll
    for (int b = 0; b < BB; b++) { float dv = z[b] - m; v = fmaf(dv, dv, v); }
    v *= (1.0f / BB);
    float rs = 1.0f / sqrtf(v + 1e-5f);
    float gg = gbn_g[d], gb = gbn_b[d];
#pragma unroll
    for (int b = 0; b < BB; b++) {
        float zn = gg * (z[b] - m) * rs + gb;
        float gate = 1.0f / (1.0f + expf(-zn));
        out[b * DD + d] = g_y[b * DD + d] * gate;
    }
}

// =====================================================================
extern "C" void kernel_launch(void* const* d_in, const int* in_sizes, int n_in,
                              void* d_out, int out_size)
{
    (void)in_sizes; (void)n_in; (void)out_size;
    const float* x      = (const float*)d_in[0];
    const float* conv_w = (const float*)d_in[1];
    const float* cent   = (const float*)d_in[2];
    const float* hw     = (const float*)d_in[3];
    const float* gw     = (const float*)d_in[4];
    const float* bn2g   = (const float*)d_in[5];
    const float* bn2b   = (const float*)d_in[6];
    const float* gbng   = (const float*)d_in[7];
    const float* gbnb   = (const float*)d_in[8];
    float* out = (float*)d_out;

    cudaFuncSetAttribute(k_logits, cudaFuncAttributeMaxDynamicSharedMemorySize, SM_TOTAL);

    // 3x k_wtb (idempotent): pads launch index so ncu capture hits k_logits
    k_wtb<<<(KK * CC + 255) / 256, 256>>>(conv_w);
    k_wtb<<<(KK * CC + 255) / 256, 256>>>(conv_w);
    k_wtb<<<(KK * CC + 255) / 256, 256>>>(conv_w);
    k_logits<<<dim3(NT128, BB), 128, SM_TOTAL>>>(x);
    k_vlad<<<dim3(SLB, BB), 256>>>(x);
    k_reduce<<<dim3(KK, BB), 256>>>(cent);
    k_hidden<<<HCH, 512>>>(hw);
    k_hreduce<<<dim3(8, BB), 256>>>();
    k_bn2<<<1, DD>>>(bn2g, bn2b);
    k_gate<<<BB, DD>>>(gw);
    k_final<<<1, DD>>>(gbng, gbnb, out);
}

// round 10
// speedup vs baseline: 1.5722x; 1.1762x over previous
#include <cuda_runtime.h>
#include <cuda_bf16.h>
#include <math.h>

#define BB 32
#define NN 4096
#define CC 256
#define KK 64
#define DD 256
#define SLB 9             /* k_vlad_t slices */
#define NCH2 64           /* 64-token chunks per batch */
#define HCH 256
#define IC 64
#define NT128 (NN/128)    /* 32 token-tiles of 128 for k_logits */

typedef unsigned long long u64;

// ---------------- device scratch ----------------
__device__ __align__(16) float  g_vpart[(size_t)BB * SLB * KK * CC];
__device__ __align__(16) float  g_asum[BB * NT128 * KK];
__device__ __align__(16) float  g_vladn[BB * KK * CC];
__device__ __align__(16) float  g_rsq[BB * KK];
__device__ __align__(16) float  g_hpart[HCH * BB * DD];
__device__ __align__(16) float  g_h[BB * DD];
__device__ __align__(16) float  g_y[BB * DD];
__device__ __align__(16) float  g_z[BB * DD];
__device__ __align__(16) __nv_bfloat16 g_wh[4 * 64 * 64];  // w hi, [kc][c][n] swizzled
__device__ __align__(16) __nv_bfloat16 g_wl[4 * 64 * 64];  // w lo
// bf16 handoff tiles (written by k_logits, read by k_vlad_t)
__device__ uint4 g_ah4[(size_t)BB * NCH2 * 512];   // a hi  [ch][64k][64t] SW128, 16 MB
__device__ uint4 g_al4[(size_t)BB * NCH2 * 512];   // a lo
__device__ uint4 g_xh4[(size_t)BB * NCH2 * 2048];  // xn hi [ch][kc][64t][64c] SW128, 64 MB
__device__ uint4 g_xl4[(size_t)BB * NCH2 * 2048];  // xn lo

// ---------------- mma.sync / ldmatrix helpers ----------------
__device__ __forceinline__ unsigned smem_u32(const void* p) {
    unsigned a;
    asm("{ .reg .u64 t; cvta.to.shared.u64 t, %1; cvt.u32.u64 %0, t; }" : "=r"(a) : "l"(p));
    return a;
}
#define SWZ(off) ((off) ^ (((off) >> 3) & 0x70))

__device__ __forceinline__ void ldsm4(unsigned* r, unsigned a) {
    asm volatile("ldmatrix.sync.aligned.m8n8.x4.shared.b16 {%0,%1,%2,%3}, [%4];"
        : "=r"(r[0]), "=r"(r[1]), "=r"(r[2]), "=r"(r[3]) : "r"(a));
}
__device__ __forceinline__ void ldsm4t(unsigned* r, unsigned a) {
    asm volatile("ldmatrix.sync.aligned.m8n8.x4.trans.shared.b16 {%0,%1,%2,%3}, [%4];"
        : "=r"(r[0]), "=r"(r[1]), "=r"(r[2]), "=r"(r[3]) : "r"(a));
}
__device__ __forceinline__ void mma16816(float* c, const unsigned* a, const unsigned* b) {
    asm volatile("mma.sync.aligned.m16n8k16.row.col.f32.bf16.bf16.f32 "
        "{%0,%1,%2,%3}, {%4,%5,%6,%7}, {%8,%9}, {%0,%1,%2,%3};"
        : "+f"(c[0]), "+f"(c[1]), "+f"(c[2]), "+f"(c[3])
        : "r"(a[0]), "r"(a[1]), "r"(a[2]), "r"(a[3]), "r"(b[0]), "r"(b[1]));
}

// smem byte offsets for k_logits
#define SM_INRM 0
#define SM_XHI  1024          /* [128t][64c] bf16 SW128 (16 KB); a_s fp32 reuses */
#define SM_XLO  17408
#define SM_WHI  33792         /* [64c][64n] bf16 SW128 (8 KB) */
#define SM_WLO  41984
#define SM_ABH  34816         /* a-bf16 build area hi (8 KB), after a_s */
#define SM_ABL  43008         /* a-bf16 build area lo */
#define SM_TOTAL 51200

// smem for k_vlad_t
#define SV_AH 0
#define SV_AL 8192
#define SV_XH 16384
#define SV_XL 49152
#define SV_TOTAL 81920

// =====================================================================
// Kernel W: split conv_w into bf16 hi/lo, layout [kc][c(64)][n=k], SW128
// =====================================================================
__global__ __launch_bounds__(256) void k_wtb(const float* __restrict__ conv_w)
{
    int idx = blockIdx.x * 256 + threadIdx.x;   // 16384
    if (idx < KK * CC) {
        int k = idx >> 8, c = idx & 255;
        int kc = c >> 6, cc = c & 63;
        float v = conv_w[k * CC + c];
        __nv_bfloat16 h = __float2bfloat16(v);
        __nv_bfloat16 l = __float2bfloat16(v - __bfloat162float(h));
        unsigned off = (unsigned)(cc * 128 + k * 2);
        unsigned sw = SWZ(off);
        *(__nv_bfloat16*)((char*)g_wh + kc * 8192 + sw) = h;
        *(__nv_bfloat16*)((char*)g_wl + kc * 8192 + sw) = l;
    }
}

// =====================================================================
// Kernel A: normalize + logits (mma.sync bf16-split) + softmax
//           emits: a bf16 hi/lo tiles, xn bf16 hi/lo tiles, asum partials
// grid = (NT128, BB), block = 128 (4 warps)
// =====================================================================
__global__ __launch_bounds__(128, 4) void k_logits(const float* __restrict__ x)
{
    extern __shared__ char smem[];
    const unsigned sb = smem_u32(smem);
    const int tid = threadIdx.x, wid = tid >> 5, lane = tid & 31;
    const int b = blockIdx.y, tile = blockIdx.x;
    const int n0 = tile * 128;
    float* inrm_s = (float*)(smem + SM_INRM);

    // --- norm pass ---
    const float4* xg4 = (const float4*)(x + ((size_t)b * NN + n0) * CC);
#pragma unroll
    for (int rep = 0; rep < 4; ++rep) {
        int t = rep * 32 + (tid >> 2), l4 = tid & 3;
        float s = 0.f;
#pragma unroll
        for (int i = 0; i < 16; ++i) {
            float4 v = xg4[t * 64 + l4 + 4 * i];
            s = fmaf(v.x, v.x, s); s = fmaf(v.y, v.y, s);
            s = fmaf(v.z, v.z, s); s = fmaf(v.w, v.w, s);
        }
        s += __shfl_xor_sync(0xffffffffu, s, 1);
        s += __shfl_xor_sync(0xffffffffu, s, 2);
        float inv = 1.0f / fmaxf(sqrtf(s), 1e-12f);
        if (l4 == 0) inrm_s[t] = inv;
    }
    __syncthreads();

    float acc[2][8][4];
#pragma unroll
    for (int mt = 0; mt < 2; ++mt)
#pragma unroll
        for (int nt = 0; nt < 8; ++nt)
#pragma unroll
            for (int e = 0; e < 4; ++e) acc[mt][nt][e] = 0.f;

    // --- K-chunk loop ---
#pragma unroll 1
    for (int kc = 0; kc < 4; ++kc) {
        const uint4* gwh = (const uint4*)((const char*)g_wh + kc * 8192);
        const uint4* gwl = (const uint4*)((const char*)g_wl + kc * 8192);
#pragma unroll
        for (int i = 0; i < 4; ++i) {
            ((uint4*)(smem + SM_WHI))[tid + 128 * i] = gwh[tid + 128 * i];
            ((uint4*)(smem + SM_WLO))[tid + 128 * i] = gwl[tid + 128 * i];
        }
#pragma unroll
        for (int r = 0; r < 8; ++r) {
            int idx = r * 128 + tid;
            int t = idx >> 3, u = idx & 7;
            float inv = inrm_s[t];
            float4 v0 = xg4[t * 64 + kc * 16 + u * 2];
            float4 v1 = xg4[t * 64 + kc * 16 + u * 2 + 1];
            float f[8] = {v0.x*inv, v0.y*inv, v0.z*inv, v0.w*inv,
                          v1.x*inv, v1.y*inv, v1.z*inv, v1.w*inv};
            unsigned hw_[4], lw_[4];
#pragma unroll
            for (int j = 0; j < 4; ++j) {
                __nv_bfloat16 h0 = __float2bfloat16(f[2*j]);
                __nv_bfloat16 h1 = __float2bfloat16(f[2*j+1]);
                __nv_bfloat16 l0 = __float2bfloat16(f[2*j]   - __bfloat162float(h0));
                __nv_bfloat16 l1 = __float2bfloat16(f[2*j+1] - __bfloat162float(h1));
                hw_[j] = ((unsigned)*(unsigned short*)&h1 << 16) | *(unsigned short*)&h0;
                lw_[j] = ((unsigned)*(unsigned short*)&l1 << 16) | *(unsigned short*)&l0;
            }
            unsigned sw = SWZ((unsigned)(t * 128 + u * 16));
            *(uint4*)(smem + SM_XHI + sw) = make_uint4(hw_[0], hw_[1], hw_[2], hw_[3]);
            *(uint4*)(smem + SM_XLO + sw) = make_uint4(lw_[0], lw_[1], lw_[2], lw_[3]);
        }
        __syncthreads();

        // MMA: 4 k16-steps
#pragma unroll
        for (int ks = 0; ks < 4; ++ks) {
            unsigned ahi[2][4], alo[2][4];
#pragma unroll
            for (int mt = 0; mt < 2; ++mt) {
                int row = wid * 32 + mt * 16 + (lane & 15);
                unsigned cb = (unsigned)(ks * 32 + ((lane >> 4) * 16));
                unsigned off = SWZ((unsigned)(row * 128) + cb);
                ldsm4(ahi[mt], sb + SM_XHI + off);
                ldsm4(alo[mt], sb + SM_XLO + off);
            }
            int krow = ks * 16 + (lane & 7) + 8 * ((lane >> 3) & 1);
            unsigned cb2 = (unsigned)((lane >> 4) * 16);
#pragma unroll
            for (int np = 0; np < 4; ++np) {
                unsigned bh[4], bl[4];
                unsigned off = SWZ((unsigned)(krow * 128) + (unsigned)(np * 32) + cb2);
                ldsm4t(bh, sb + SM_WHI + off);
                ldsm4t(bl, sb + SM_WLO + off);
#pragma unroll
                for (int mt = 0; mt < 2; ++mt) {
                    mma16816(acc[mt][2*np],     ahi[mt], bh);
                    mma16816(acc[mt][2*np],     ahi[mt], bl);
                    mma16816(acc[mt][2*np],     alo[mt], bh);
                    mma16816(acc[mt][2*np+1],   ahi[mt], bh + 2);
                    mma16816(acc[mt][2*np+1],   ahi[mt], bl + 2);
                    mma16816(acc[mt][2*np+1],   alo[mt], bh + 2);
                }
            }
        }

        // dump xn bf16 tiles (reads x_s; concurrent with nothing that writes it)
        {
            const uint4* sxh = (const uint4*)(smem + SM_XHI);
            const uint4* sxl = (const uint4*)(smem + SM_XLO);
            size_t chA = ((size_t)(b * NCH2 + tile * 2) * 4 + kc) * 512;
            size_t chB = ((size_t)(b * NCH2 + tile * 2 + 1) * 4 + kc) * 512;
            for (int i = tid; i < 1024; i += 128) {
                size_t dst = (i < 512) ? (chA + i) : (chB + (i - 512));
                g_xh4[dst] = sxh[i];
                g_xl4[dst] = sxl[i];
            }
        }
        __syncthreads();
    }

    // --- epilogue: softmax per token, stage a_s (fp32) ---
    const int g = lane >> 2, tg = lane & 3;
    float* a_s = (float*)(smem + SM_XHI);   // 64 x 130 floats
#pragma unroll
    for (int mt = 0; mt < 2; ++mt) {
#pragma unroll
        for (int i = 0; i < 2; ++i) {
            float mx = -1e30f;
#pragma unroll
            for (int nt = 0; nt < 8; ++nt) {
                mx = fmaxf(mx, acc[mt][nt][2*i]);
                mx = fmaxf(mx, acc[mt][nt][2*i+1]);
            }
            mx = fmaxf(mx, __shfl_xor_sync(0xffffffffu, mx, 1));
            mx = fmaxf(mx, __shfl_xor_sync(0xffffffffu, mx, 2));
            float se = 0.f;
#pragma unroll
            for (int nt = 0; nt < 8; ++nt) {
                acc[mt][nt][2*i]   = expf(acc[mt][nt][2*i]   - mx);
                acc[mt][nt][2*i+1] = expf(acc[mt][nt][2*i+1] - mx);
                se += acc[mt][nt][2*i] + acc[mt][nt][2*i+1];
            }
            se += __shfl_xor_sync(0xffffffffu, se, 1);
            se += __shfl_xor_sync(0xffffffffu, se, 2);
            float inv = 1.0f / se;
            int t = wid * 32 + mt * 16 + 8 * i + g;
#pragma unroll
            for (int nt = 0; nt < 8; ++nt) {
                a_s[(nt*8 + 2*tg    ) * 130 + t] = acc[mt][nt][2*i]   * inv;
                a_s[(nt*8 + 2*tg + 1) * 130 + t] = acc[mt][nt][2*i+1] * inv;
            }
        }
    }
    __syncthreads();

    // asum partials: thread k sums its row over 128 tokens
    if (tid < 64) {
        float s = 0.f;
#pragma unroll 8
        for (int t = 0; t < 128; ++t) s += a_s[tid * 130 + t];
        g_asum[(b * NT128 + tile) * KK + tid] = s;
    }

    // build + dump a bf16 hi/lo tiles [64k][64t] SW128, per 64-token chunk
#pragma unroll 1
    for (int ch2 = 0; ch2 < 2; ++ch2) {
        for (int i = tid; i < 4096; i += 128) {
            int k = i >> 6, t = i & 63;
            float v = a_s[k * 130 + ch2 * 64 + t];
            __nv_bfloat16 h = __float2bfloat16(v);
            __nv_bfloat16 l = __float2bfloat16(v - __bfloat162float(h));
            unsigned sw = SWZ((unsigned)(k * 128 + t * 2));
            *(__nv_bfloat16*)(smem + SM_ABH + sw) = h;
            *(__nv_bfloat16*)(smem + SM_ABL + sw) = l;
        }
        __syncthreads();
        size_t dst = (size_t)(b * NCH2 + tile * 2 + ch2) * 512;
        const uint4* sh = (const uint4*)(smem + SM_ABH);
        const uint4* sl = (const uint4*)(smem + SM_ABL);
        for (int i = tid; i < 512; i += 128) {
            g_ah4[dst + i] = sh[i];
            g_al4[dst + i] = sl[i];
        }
        __syncthreads();
    }
}

// =====================================================================
// Kernel B: VLAD via mma.sync: V[64k][256c] += a[k][t] xn[t][c]
// grid = (SLB, BB), block = 256 (8 warps, warp = 32-c slice), 2 CTA/SM
// =====================================================================
__global__ __launch_bounds__(256, 2) void k_vlad_t()
{
    extern __shared__ char smem[];
    const unsigned sb = smem_u32(smem);
    const int tid = threadIdx.x, warp = tid >> 5, lane = tid & 31;
    const int b = blockIdx.y, sl = blockIdx.x;

    float acc[4][4][4];
#pragma unroll
    for (int mt = 0; mt < 4; ++mt)
#pragma unroll
        for (int nt = 0; nt < 4; ++nt)
#pragma unroll
            for (int e = 0; e < 4; ++e) acc[mt][nt][e] = 0.f;

    const int kcw = warp >> 1;          // c-chunk of this warp
    const unsigned cwb = (unsigned)((warp & 1) * 64);  // col-byte base in chunk

#pragma unroll 1
    for (int ch = sl; ch < NCH2; ch += SLB) {
        __syncthreads();
        // stage: a 1024 uint4, x 4096 uint4
        {
            const uint4* gah = g_ah4 + (size_t)(b * NCH2 + ch) * 512;
            const uint4* gal = g_al4 + (size_t)(b * NCH2 + ch) * 512;
            const uint4* gxh = g_xh4 + (size_t)(b * NCH2 + ch) * 2048;
            const uint4* gxl = g_xl4 + (size_t)(b * NCH2 + ch) * 2048;
            uint4* sa_h = (uint4*)(smem + SV_AH);
            uint4* sa_l = (uint4*)(smem + SV_AL);
            uint4* sx_h = (uint4*)(smem + SV_XH);
            uint4* sx_l = (uint4*)(smem + SV_XL);
#pragma unroll
            for (int i = 0; i < 2; ++i) {
                sa_h[tid + 256 * i] = gah[tid + 256 * i];
                sa_l[tid + 256 * i] = gal[tid + 256 * i];
            }
#pragma unroll
            for (int i = 0; i < 8; ++i) {
                sx_h[tid + 256 * i] = gxh[tid + 256 * i];
                sx_l[tid + 256 * i] = gxl[tid + 256 * i];
            }
        }
        __syncthreads();

        const unsigned xbase_h = sb + SV_XH + kcw * 8192;
        const unsigned xbase_l = sb + SV_XL + kcw * 8192;
        const int krow0 = (lane & 7) + 8 * ((lane >> 3) & 1);
        const unsigned cb2 = cwb + (unsigned)((lane >> 4) * 16);

#pragma unroll
        for (int ks = 0; ks < 4; ++ks) {
            // B frags: xn [64t][64c] tiles, trans -> [c][t]
            unsigned bh[2][4], bl[2][4];
            int krow = ks * 16 + krow0;
#pragma unroll
            for (int h = 0; h < 2; ++h) {
                unsigned off = SWZ((unsigned)(krow * 128) + h * 32 + cb2);
                ldsm4t(bh[h], xbase_h + off);
                ldsm4t(bl[h], xbase_l + off);
            }
            // A frags per mt, then 12 MMAs
#pragma unroll
            for (int mt = 0; mt < 4; ++mt) {
                unsigned Ah[4], Al[4];
                int row = mt * 16 + (lane & 15);
                unsigned off = SWZ((unsigned)(row * 128) + (unsigned)(ks * 32 + ((lane >> 4) * 16)));
                ldsm4(Ah, sb + SV_AH + off);
                ldsm4(Al, sb + SV_AL + off);
#pragma unroll
                for (int h = 0; h < 2; ++h) {
#pragma unroll
                    for (int j2 = 0; j2 < 2; ++j2) {
                        float* C = acc[mt][h * 2 + j2];
                        mma16816(C, Ah, bh[h] + 2 * j2);
                        mma16816(C, Ah, bl[h] + 2 * j2);
                        mma16816(C, Al, bh[h] + 2 * j2);
                    }
                }
            }
        }
    }

    // epilogue: write V partials fp32
    float* vp = g_vpart + ((size_t)(b * SLB + sl) * KK) * CC;
#pragma unroll
    for (int mt = 0; mt < 4; ++mt) {
#pragma unroll
        for (int nt = 0; nt < 4; ++nt) {
            int k0 = mt * 16 + (lane >> 2);
            int c0 = warp * 32 + nt * 8 + (lane & 3) * 2;
            *(float2*)(vp + (size_t)k0 * CC + c0)       = make_float2(acc[mt][nt][0], acc[mt][nt][1]);
            *(float2*)(vp + (size_t)(k0 + 8) * CC + c0) = make_float2(acc[mt][nt][2], acc[mt][nt][3]);
        }
    }
}

// =====================================================================
// Kernel 2: reduce slices + centroid subtract + intra L2 norm
// =====================================================================
__global__ __launch_bounds__(256) void k_reduce(const float* __restrict__ cent)
{
    const int k = blockIdx.x, b = blockIdx.y, c = threadIdx.x;
    float vs = 0.f;
#pragma unroll 3
    for (int s = 0; s < SLB; ++s)
        vs += g_vpart[(((size_t)b * SLB + s) * KK + k) * CC + c];
    float as = 0.f;
#pragma unroll 4
    for (int s = 0; s < NT128; ++s)
        as += g_asum[(b * NT128 + s) * KK + k];
    float v = vs - as * cent[k * CC + c];

    __shared__ float red[8];
    float sq = v * v;
#pragma unroll
    for (int o = 16; o; o >>= 1) sq += __shfl_xor_sync(0xffffffffu, sq, o);
    if ((threadIdx.x & 31) == 0) red[threadIdx.x >> 5] = sq;
    __syncthreads();
    float tot = 0.f;
#pragma unroll
    for (int w = 0; w < 8; w++) tot += red[w];
    float inv = 1.0f / fmaxf(sqrtf(tot), 1e-12f);
    g_vladn[((size_t)b * KK + k) * CC + c] = v * inv;
    if (c == 0) g_rsq[b * KK + k] = tot * inv * inv;
}

// =====================================================================
// Kernel 3: hidden GEMM partials
// =====================================================================
__global__ __launch_bounds__(512, 2) void k_hidden(const float* __restrict__ hw)
{
    __shared__ float vs_s[BB * IC];
    __shared__ float ps[BB * DD];
    const int i0 = blockIdx.x * IC;
    const int tid = threadIdx.x;
    const int d = tid & 255, g = tid >> 8;

    for (int idx = tid; idx < BB * IC; idx += 512) {
        int bb = idx >> 6, ii = idx & 63;
        vs_s[idx] = g_vladn[(size_t)bb * (KK * CC) + i0 + ii];
    }
    __syncthreads();

    float P[BB];
#pragma unroll
    for (int bb = 0; bb < BB; bb++) P[bb] = 0.f;

    const float* wp = hw + (size_t)(i0 + g * 32) * DD + d;
#pragma unroll
    for (int i = 0; i < 32; ++i) {
        float w = wp[(size_t)i * DD];
        int ii = g * 32 + i;
#pragma unroll
        for (int bb = 0; bb < BB; bb++) P[bb] = fmaf(vs_s[bb * IC + ii], w, P[bb]);
    }

    if (g == 1) {
#pragma unroll
        for (int bb = 0; bb < BB; bb++) ps[bb * DD + d] = P[bb];
    }
    __syncthreads();
    if (g == 0) {
#pragma unroll
        for (int bb = 0; bb < BB; bb++)
            g_hpart[((size_t)blockIdx.x * BB + bb) * DD + d] = P[bb] + ps[bb * DD + d];
    }
}

// =====================================================================
// Kernel 4: reduce hidden partials + global inv-norm
// =====================================================================
__global__ __launch_bounds__(256) void k_hreduce()
{
    __shared__ float red[8 * 33];
    const int b = blockIdx.y, dg = blockIdx.x;
    const int dl = threadIdx.x & 31, s8 = threadIdx.x >> 5;
    const int d = dg * 32 + dl;

    float inv = 0.f;
    if (s8 == 0) {
        float s = g_rsq[b * KK + dl] + g_rsq[b * KK + 32 + dl];
#pragma unroll
        for (int o = 16; o; o >>= 1) s += __shfl_xor_sync(0xffffffffu, s, o);
        inv = 1.0f / fmaxf(sqrtf(s), 1e-12f);
    }

    float s = 0.f;
#pragma unroll 8
    for (int ch = s8; ch < HCH; ch += 8)
        s += g_hpart[((size_t)ch * BB + b) * DD + d];
    red[s8 * 33 + dl] = s;
    __syncthreads();
    if (s8 == 0) {
        float t = 0.f;
#pragma unroll
        for (int w = 0; w < 8; w++) t += red[w * 33 + dl];
        g_h[b * DD + d] = t * inv;
    }
}

// =====================================================================
// Kernel 5/6/7: BN2, gating GEMM, final
// =====================================================================
__global__ __launch_bounds__(DD) void k_bn2(const float* __restrict__ gamma,
                                            const float* __restrict__ beta)
{
    const int d = threadIdx.x;
    float y[BB];
    float m = 0.f;
#pragma unroll
    for (int b = 0; b < BB; b++) { y[b] = g_h[b * DD + d]; m += y[b]; }
    m *= (1.0f / BB);
    float v = 0.f;
#pragma unroll
    for (int b = 0; b < BB; b++) { float dv = y[b] - m; v = fmaf(dv, dv, v); }
    v *= (1.0f / BB);
    float rs = 1.0f / sqrtf(v + 1e-5f);
    float ga = gamma[d], be = beta[d];
#pragma unroll
    for (int b = 0; b < BB; b++)
        g_y[b * DD + d] = ga * (y[b] - m) * rs + be;
}

__global__ __launch_bounds__(DD) void k_gate(const float* __restrict__ gw)
{
    __shared__ float yb[DD];
    const int b = blockIdx.x, d = threadIdx.x;
    yb[d] = g_y[b * DD + d];
    __syncthreads();
    float z = 0.f;
#pragma unroll 4
    for (int dd = 0; dd < DD; ++dd) z = fmaf(yb[dd], gw[dd * DD + d], z);
    g_z[b * DD + d] = z;
}

__global__ __launch_bounds__(DD) void k_final(const float* __restrict__ gbn_g,
                                              const float* __restrict__ gbn_b,
                                              float* __restrict__ out)
{
    const int d = threadIdx.x;
    float z[BB];
    float m = 0.f;
#pragma unroll
    for (int b = 0; b < BB; b++) { z[b] = g_z[b * DD + d]; m += z[b]; }
    m *= (1.0f / BB);
    float v = 0.f;
#pragma unroll
    for (int b = 0; b < BB; b++) { float dv = z[b] - m; v = fmaf(dv, dv, v); }
    v *= (1.0f / BB);
    float rs = 1.0f / sqrtf(v + 1e-5f);
    float gg = gbn_g[d], gb = gbn_b[d];
#pragma unroll
    for (int b = 0; b < BB; b++) {
        float zn = gg * (z[b] - m) * rs + gb;
        float gate = 1.0f / (1.0f + expf(-zn));
        out[b * DD + d] = g_y[b * DD + d] * gate;
    }
}

// =====================================================================
extern "C" void kernel_launch(void* const* d_in, const int* in_sizes, int n_in,
                              void* d_out, int out_size)
{
    (void)in_sizes; (void)n_in; (void)out_size;
    const float* x      = (const float*)d_in[0];
    const float* conv_w = (const float*)d_in[1];
    const float* cent   = (const float*)d_in[2];
    const float* hw     = (const float*)d_in[3];
    const float* gw     = (const float*)d_in[4];
    const float* bn2g   = (const float*)d_in[5];
    const float* bn2b   = (const float*)d_in[6];
    const float* gbng   = (const float*)d_in[7];
    const float* gbnb   = (const float*)d_in[8];
    float* out = (float*)d_out;

    cudaFuncSetAttribute(k_logits, cudaFuncAttributeMaxDynamicSharedMemorySize, SM_TOTAL);
    cudaFuncSetAttribute(k_vlad_t, cudaFuncAttributeMaxDynamicSharedMemorySize, SV_TOTAL);

    // launch idx 3 = k_vlad_t (ncu capture slot); k_wtb idempotent pad at idx 2
    k_wtb<<<(KK * CC + 255) / 256, 256>>>(conv_w);
    k_logits<<<dim3(NT128, BB), 128, SM_TOTAL>>>(x);
    k_wtb<<<(KK * CC + 255) / 256, 256>>>(conv_w);
    k_vlad_t<<<dim3(SLB, BB), 256, SV_TOTAL>>>();
    k_reduce<<<dim3(KK, BB), 256>>>(cent);
    k_hidden<<<HCH, 512>>>(hw);
    k_hreduce<<<dim3(8, BB), 256>>>();
    k_bn2<<<1, DD>>>(bn2g, bn2b);
    k_gate<<<BB, DD>>>(gw);
    k_final<<<1, DD>>>(gbng, gbnb, out);
}

// round 13
// speedup vs baseline: 1.6331x; 1.0388x over previous
#include <cuda_runtime.h>
#include <cuda_bf16.h>
#include <math.h>

#define BB 32
#define NN 4096
#define CC 256
#define KK 64
#define DD 256
#define SLB 9             /* k_vlad_t slices */
#define NCH2 64           /* 64-token chunks per batch */
#define HCH 256
#define IC 64
#define NT128 (NN/128)    /* 32 token-tiles of 128 for k_logits */

typedef unsigned long long u64;

// ---------------- device scratch ----------------
__device__ __align__(16) float  g_vpart[(size_t)BB * SLB * KK * CC];
__device__ __align__(16) float  g_asum[BB * NT128 * KK];
__device__ __align__(16) float  g_inrm[BB * NN];
__device__ __align__(16) float  g_vladn[BB * KK * CC];
__device__ __align__(16) float  g_rsq[BB * KK];
__device__ __align__(16) float  g_hpart[HCH * BB * DD];
__device__ __align__(16) float  g_h[BB * DD];
__device__ __align__(16) float  g_y[BB * DD];
__device__ __align__(16) float  g_z[BB * DD];
__device__ __align__(16) __nv_bfloat16 g_wh[4 * 64 * 64];  // w hi, [kc][c][n] swizzled
__device__ __align__(16) __nv_bfloat16 g_wl[4 * 64 * 64];  // w lo
// bf16 handoff tiles for a only (xn recomputed in k_vlad_t)
__device__ uint4 g_ah4[(size_t)BB * NCH2 * 512];   // a hi  [ch][64k][64t] SW128, 16 MB
__device__ uint4 g_al4[(size_t)BB * NCH2 * 512];   // a lo

// ---------------- mma.sync / ldmatrix helpers ----------------
__device__ __forceinline__ unsigned smem_u32(const void* p) {
    unsigned a;
    asm("{ .reg .u64 t; cvta.to.shared.u64 t, %1; cvt.u32.u64 %0, t; }" : "=r"(a) : "l"(p));
    return a;
}
#define SWZ(off) ((off) ^ (((off) >> 3) & 0x70))

__device__ __forceinline__ void ldsm4(unsigned* r, unsigned a) {
    asm volatile("ldmatrix.sync.aligned.m8n8.x4.shared.b16 {%0,%1,%2,%3}, [%4];"
        : "=r"(r[0]), "=r"(r[1]), "=r"(r[2]), "=r"(r[3]) : "r"(a));
}
__device__ __forceinline__ void ldsm4t(unsigned* r, unsigned a) {
    asm volatile("ldmatrix.sync.aligned.m8n8.x4.trans.shared.b16 {%0,%1,%2,%3}, [%4];"
        : "=r"(r[0]), "=r"(r[1]), "=r"(r[2]), "=r"(r[3]) : "r"(a));
}
__device__ __forceinline__ void mma16816(float* c, const unsigned* a, const unsigned* b) {
    asm volatile("mma.sync.aligned.m16n8k16.row.col.f32.bf16.bf16.f32 "
        "{%0,%1,%2,%3}, {%4,%5,%6,%7}, {%8,%9}, {%0,%1,%2,%3};"
        : "+f"(c[0]), "+f"(c[1]), "+f"(c[2]), "+f"(c[3])
        : "r"(a[0]), "r"(a[1]), "r"(a[2]), "r"(a[3]), "r"(b[0]), "r"(b[1]));
}
// split 8 scaled floats into packed bf16 hi/lo uint4s
__device__ __forceinline__ void split8(const float* f, uint4& hi, uint4& lo) {
    unsigned hw_[4], lw_[4];
#pragma unroll
    for (int j = 0; j < 4; ++j) {
        __nv_bfloat16 h0 = __float2bfloat16(f[2*j]);
        __nv_bfloat16 h1 = __float2bfloat16(f[2*j+1]);
        __nv_bfloat16 l0 = __float2bfloat16(f[2*j]   - __bfloat162float(h0));
        __nv_bfloat16 l1 = __float2bfloat16(f[2*j+1] - __bfloat162float(h1));
        hw_[j] = ((unsigned)*(unsigned short*)&h1 << 16) | *(unsigned short*)&h0;
        lw_[j] = ((unsigned)*(unsigned short*)&l1 << 16) | *(unsigned short*)&l0;
    }
    hi = make_uint4(hw_[0], hw_[1], hw_[2], hw_[3]);
    lo = make_uint4(lw_[0], lw_[1], lw_[2], lw_[3]);
}

// smem byte offsets for k_logits
#define SM_INRM 0
#define SM_XHI  1024          /* [128t][64c] bf16 SW128 (16 KB); a_s fp32 reuses */
#define SM_XLO  17408
#define SM_WHI  33792         /* [64c][64n] bf16 SW128 (8 KB) */
#define SM_WLO  41984
#define SM_ABH  34816         /* a-bf16 build area hi (reuses w space post-loop) */
#define SM_ABL  43008
#define SM_TOTAL 51200

// smem for k_vlad_t
#define SV_AH 0
#define SV_AL 8192
#define SV_XH 16384           /* 4 kc tiles x [64t][64c] bf16 SW128 (32 KB) */
#define SV_XL 49152
#define SV_TOTAL 81920

// =====================================================================
// Kernel W: split conv_w into bf16 hi/lo, layout [kc][c(64)][n=k], SW128
// =====================================================================
__global__ __launch_bounds__(256) void k_wtb(const float* __restrict__ conv_w)
{
    int idx = blockIdx.x * 256 + threadIdx.x;   // 16384
    if (idx < KK * CC) {
        int k = idx >> 8, c = idx & 255;
        int kc = c >> 6, cc = c & 63;
        float v = conv_w[k * CC + c];
        __nv_bfloat16 h = __float2bfloat16(v);
        __nv_bfloat16 l = __float2bfloat16(v - __bfloat162float(h));
        unsigned off = (unsigned)(cc * 128 + k * 2);
        unsigned sw = SWZ(off);
        *(__nv_bfloat16*)((char*)g_wh + kc * 8192 + sw) = h;
        *(__nv_bfloat16*)((char*)g_wl + kc * 8192 + sw) = l;
    }
}

// =====================================================================
// Kernel A: normalize + logits (mma.sync bf16-split) + softmax
//           emits: g_a bf16 tiles, g_asum partials, g_inrm
// grid = (NT128, BB), block = 128 (4 warps)
// =====================================================================
__global__ __launch_bounds__(128, 4) void k_logits(const float* __restrict__ x)
{
    extern __shared__ char smem[];
    const unsigned sb = smem_u32(smem);
    const int tid = threadIdx.x, wid = tid >> 5, lane = tid & 31;
    const int b = blockIdx.y, tile = blockIdx.x;
    const int n0 = tile * 128;
    float* inrm_s = (float*)(smem + SM_INRM);

    // --- norm pass ---
    const float4* xg4 = (const float4*)(x + ((size_t)b * NN + n0) * CC);
#pragma unroll
    for (int rep = 0; rep < 4; ++rep) {
        int t = rep * 32 + (tid >> 2), l4 = tid & 3;
        float s = 0.f;
#pragma unroll
        for (int i = 0; i < 16; ++i) {
            float4 v = xg4[t * 64 + l4 + 4 * i];
            s = fmaf(v.x, v.x, s); s = fmaf(v.y, v.y, s);
            s = fmaf(v.z, v.z, s); s = fmaf(v.w, v.w, s);
        }
        s += __shfl_xor_sync(0xffffffffu, s, 1);
        s += __shfl_xor_sync(0xffffffffu, s, 2);
        float inv = 1.0f / fmaxf(sqrtf(s), 1e-12f);
        if (l4 == 0) { inrm_s[t] = inv; g_inrm[b * NN + n0 + t] = inv; }
    }
    __syncthreads();

    float acc[2][8][4];
#pragma unroll
    for (int mt = 0; mt < 2; ++mt)
#pragma unroll
        for (int nt = 0; nt < 8; ++nt)
#pragma unroll
            for (int e = 0; e < 4; ++e) acc[mt][nt][e] = 0.f;

    // --- K-chunk loop ---
#pragma unroll 1
    for (int kc = 0; kc < 4; ++kc) {
        const uint4* gwh = (const uint4*)((const char*)g_wh + kc * 8192);
        const uint4* gwl = (const uint4*)((const char*)g_wl + kc * 8192);
#pragma unroll
        for (int i = 0; i < 4; ++i) {
            ((uint4*)(smem + SM_WHI))[tid + 128 * i] = gwh[tid + 128 * i];
            ((uint4*)(smem + SM_WLO))[tid + 128 * i] = gwl[tid + 128 * i];
        }
#pragma unroll
        for (int r = 0; r < 8; ++r) {
            int idx = r * 128 + tid;
            int t = idx >> 3, u = idx & 7;
            float inv = inrm_s[t];
            float4 v0 = xg4[t * 64 + kc * 16 + u * 2];
            float4 v1 = xg4[t * 64 + kc * 16 + u * 2 + 1];
            float f[8] = {v0.x*inv, v0.y*inv, v0.z*inv, v0.w*inv,
                          v1.x*inv, v1.y*inv, v1.z*inv, v1.w*inv};
            uint4 hi, lo;
            split8(f, hi, lo);
            unsigned sw = SWZ((unsigned)(t * 128 + u * 16));
            *(uint4*)(smem + SM_XHI + sw) = hi;
            *(uint4*)(smem + SM_XLO + sw) = lo;
        }
        __syncthreads();

        // MMA: 4 k16-steps
#pragma unroll
        for (int ks = 0; ks < 4; ++ks) {
            unsigned ahi[2][4], alo[2][4];
#pragma unroll
            for (int mt = 0; mt < 2; ++mt) {
                int row = wid * 32 + mt * 16 + (lane & 15);
                unsigned cb = (unsigned)(ks * 32 + ((lane >> 4) * 16));
                unsigned off = SWZ((unsigned)(row * 128) + cb);
                ldsm4(ahi[mt], sb + SM_XHI + off);
                ldsm4(alo[mt], sb + SM_XLO + off);
            }
            int krow = ks * 16 + (lane & 7) + 8 * ((lane >> 3) & 1);
            unsigned cb2 = (unsigned)((lane >> 4) * 16);
#pragma unroll
            for (int np = 0; np < 4; ++np) {
                unsigned bh[4], bl[4];
                unsigned off = SWZ((unsigned)(krow * 128) + (unsigned)(np * 32) + cb2);
                ldsm4t(bh, sb + SM_WHI + off);
                ldsm4t(bl, sb + SM_WLO + off);
#pragma unroll
                for (int mt = 0; mt < 2; ++mt) {
                    mma16816(acc[mt][2*np],     ahi[mt], bh);
                    mma16816(acc[mt][2*np],     ahi[mt], bl);
                    mma16816(acc[mt][2*np],     alo[mt], bh);
                    mma16816(acc[mt][2*np+1],   ahi[mt], bh + 2);
                    mma16816(acc[mt][2*np+1],   ahi[mt], bl + 2);
                    mma16816(acc[mt][2*np+1],   alo[mt], bh + 2);
                }
            }
        }
        __syncthreads();
    }

    // --- epilogue: softmax per token, stage a_s (fp32) ---
    const int g = lane >> 2, tg = lane & 3;
    float* a_s = (float*)(smem + SM_XHI);   // 64 x 130 floats
#pragma unroll
    for (int mt = 0; mt < 2; ++mt) {
#pragma unroll
        for (int i = 0; i < 2; ++i) {
            float mx = -1e30f;
#pragma unroll
            for (int nt = 0; nt < 8; ++nt) {
                mx = fmaxf(mx, acc[mt][nt][2*i]);
                mx = fmaxf(mx, acc[mt][nt][2*i+1]);
            }
            mx = fmaxf(mx, __shfl_xor_sync(0xffffffffu, mx, 1));
            mx = fmaxf(mx, __shfl_xor_sync(0xffffffffu, mx, 2));
            float se = 0.f;
#pragma unroll
            for (int nt = 0; nt < 8; ++nt) {
                acc[mt][nt][2*i]   = expf(acc[mt][nt][2*i]   - mx);
                acc[mt][nt][2*i+1] = expf(acc[mt][nt][2*i+1] - mx);
                se += acc[mt][nt][2*i] + acc[mt][nt][2*i+1];
            }
            se += __shfl_xor_sync(0xffffffffu, se, 1);
            se += __shfl_xor_sync(0xffffffffu, se, 2);
            float inv = 1.0f / se;
            int t = wid * 32 + mt * 16 + 8 * i + g;
#pragma unroll
            for (int nt = 0; nt < 8; ++nt) {
                a_s[(nt*8 + 2*tg    ) * 130 + t] = acc[mt][nt][2*i]   * inv;
                a_s[(nt*8 + 2*tg + 1) * 130 + t] = acc[mt][nt][2*i+1] * inv;
            }
        }
    }
    __syncthreads();

    // asum partials
    if (tid < 64) {
        float s = 0.f;
#pragma unroll 8
        for (int t = 0; t < 128; ++t) s += a_s[tid * 130 + t];
        g_asum[(b * NT128 + tile) * KK + tid] = s;
    }

    // build + dump a bf16 hi/lo tiles [64k][64t] SW128, per 64-token chunk
#pragma unroll 1
    for (int ch2 = 0; ch2 < 2; ++ch2) {
        for (int i = tid; i < 4096; i += 128) {
            int k = i >> 6, t = i & 63;
            float v = a_s[k * 130 + ch2 * 64 + t];
            __nv_bfloat16 h = __float2bfloat16(v);
            __nv_bfloat16 l = __float2bfloat16(v - __bfloat162float(h));
            unsigned sw = SWZ((unsigned)(k * 128 + t * 2));
            *(__nv_bfloat16*)(smem + SM_ABH + sw) = h;
            *(__nv_bfloat16*)(smem + SM_ABL + sw) = l;
        }
        __syncthreads();
        size_t dst = (size_t)(b * NCH2 + tile * 2 + ch2) * 512;
        const uint4* sh = (const uint4*)(smem + SM_ABH);
        const uint4* sl = (const uint4*)(smem + SM_ABL);
        for (int i = tid; i < 512; i += 128) {
            g_ah4[dst + i] = sh[i];
            g_al4[dst + i] = sl[i];
        }
        __syncthreads();
    }
}

// =====================================================================
// Kernel B: VLAD via mma.sync: V[64k][256c] += a[k][t] xn[t][c]
// xn bf16 tiles recomputed in-kernel from x + g_inrm (saves 128 MB handoff)
// grid = (SLB, BB), block = 256 (8 warps), 2 CTA/SM
// =====================================================================
__global__ __launch_bounds__(256, 2) void k_vlad_t(const float* __restrict__ x)
{
    extern __shared__ char smem[];
    const unsigned sb = smem_u32(smem);
    const int tid = threadIdx.x, warp = tid >> 5, lane = tid & 31;
    const int b = blockIdx.y, sl = blockIdx.x;

    float acc[4][4][4];
#pragma unroll
    for (int mt = 0; mt < 4; ++mt)
#pragma unroll
        for (int nt = 0; nt < 4; ++nt)
#pragma unroll
            for (int e = 0; e < 4; ++e) acc[mt][nt][e] = 0.f;

    const int kcw = warp >> 1;
    const unsigned cwb = (unsigned)((warp & 1) * 64);

#pragma unroll 1
    for (int ch = sl; ch < NCH2; ch += SLB) {
        __syncthreads();
        // stage a tiles (memcpy)
        {
            const uint4* gah = g_ah4 + (size_t)(b * NCH2 + ch) * 512;
            const uint4* gal = g_al4 + (size_t)(b * NCH2 + ch) * 512;
            uint4* sa_h = (uint4*)(smem + SV_AH);
            uint4* sa_l = (uint4*)(smem + SV_AL);
#pragma unroll
            for (int i = 0; i < 2; ++i) {
                sa_h[tid + 256 * i] = gah[tid + 256 * i];
                sa_l[tid + 256 * i] = gal[tid + 256 * i];
            }
        }
        // stage xn tiles: load x fp32, normalize, bf16-split, swizzle-store
        {
            const float4* xg4 = (const float4*)(x + ((size_t)b * NN + ch * 64) * CC);
            const float* ing = g_inrm + b * NN + ch * 64;
#pragma unroll
            for (int r = 0; r < 8; ++r) {
                int idx = r * 256 + tid;       // 0..2047
                int t = idx >> 5;              // token 0..63 (one per warp -> bcast inrm)
                int c8 = idx & 31;             // 8-float group
                float inv = ing[t];
                float4 v0 = xg4[t * 64 + c8 * 2];
                float4 v1 = xg4[t * 64 + c8 * 2 + 1];
                float f[8] = {v0.x*inv, v0.y*inv, v0.z*inv, v0.w*inv,
                              v1.x*inv, v1.y*inv, v1.z*inv, v1.w*inv};
                uint4 hi, lo;
                split8(f, hi, lo);
                int kc = c8 >> 3, u = c8 & 7;
                unsigned sw = SWZ((unsigned)(t * 128 + u * 16));
                *(uint4*)(smem + SV_XH + kc * 8192 + sw) = hi;
                *(uint4*)(smem + SV_XL + kc * 8192 + sw) = lo;
            }
        }
        __syncthreads();

        const unsigned xbase_h = sb + SV_XH + kcw * 8192;
        const unsigned xbase_l = sb + SV_XL + kcw * 8192;
        const int krow0 = (lane & 7) + 8 * ((lane >> 3) & 1);
        const unsigned cb2 = cwb + (unsigned)((lane >> 4) * 16);

#pragma unroll
        for (int ks = 0; ks < 4; ++ks) {
            unsigned bh[2][4], bl[2][4];
            int krow = ks * 16 + krow0;
#pragma unroll
            for (int h = 0; h < 2; ++h) {
                unsigned off = SWZ((unsigned)(krow * 128) + h * 32 + cb2);
                ldsm4t(bh[h], xbase_h + off);
                ldsm4t(bl[h], xbase_l + off);
            }
#pragma unroll
            for (int mt = 0; mt < 4; ++mt) {
                unsigned Ah[4], Al[4];
                int row = mt * 16 + (lane & 15);
                unsigned off = SWZ((unsigned)(row * 128) + (unsigned)(ks * 32 + ((lane >> 4) * 16)));
                ldsm4(Ah, sb + SV_AH + off);
                ldsm4(Al, sb + SV_AL + off);
#pragma unroll
                for (int h = 0; h < 2; ++h) {
#pragma unroll
                    for (int j2 = 0; j2 < 2; ++j2) {
                        float* C = acc[mt][h * 2 + j2];
                        mma16816(C, Ah, bh[h] + 2 * j2);
                        mma16816(C, Ah, bl[h] + 2 * j2);
                        mma16816(C, Al, bh[h] + 2 * j2);
                    }
                }
            }
        }
    }

    // epilogue: write V partials fp32
    float* vp = g_vpart + ((size_t)(b * SLB + sl) * KK) * CC;
#pragma unroll
    for (int mt = 0; mt < 4; ++mt) {
#pragma unroll
        for (int nt = 0; nt < 4; ++nt) {
            int k0 = mt * 16 + (lane >> 2);
            int c0 = warp * 32 + nt * 8 + (lane & 3) * 2;
            *(float2*)(vp + (size_t)k0 * CC + c0)       = make_float2(acc[mt][nt][0], acc[mt][nt][1]);
            *(float2*)(vp + (size_t)(k0 + 8) * CC + c0) = make_float2(acc[mt][nt][2], acc[mt][nt][3]);
        }
    }
}

// =====================================================================
// Kernel 2: reduce slices + centroid subtract + intra L2 norm
// =====================================================================
__global__ __launch_bounds__(256) void k_reduce(const float* __restrict__ cent)
{
    const int k = blockIdx.x, b = blockIdx.y, c = threadIdx.x;
    float vs = 0.f;
#pragma unroll 3
    for (int s = 0; s < SLB; ++s)
        vs += g_vpart[(((size_t)b * SLB + s) * KK + k) * CC + c];
    float as = 0.f;
#pragma unroll 4
    for (int s = 0; s < NT128; ++s)
        as += g_asum[(b * NT128 + s) * KK + k];
    float v = vs - as * cent[k * CC + c];

    __shared__ float red[8];
    float sq = v * v;
#pragma unroll
    for (int o = 16; o; o >>= 1) sq += __shfl_xor_sync(0xffffffffu, sq, o);
    if ((threadIdx.x & 31) == 0) red[threadIdx.x >> 5] = sq;
    __syncthreads();
    float tot = 0.f;
#pragma unroll
    for (int w = 0; w < 8; w++) tot += red[w];
    float inv = 1.0f / fmaxf(sqrtf(tot), 1e-12f);
    g_vladn[((size_t)b * KK + k) * CC + c] = v * inv;
    if (c == 0) g_rsq[b * KK + k] = tot * inv * inv;
}

// =====================================================================
// Kernel 3: hidden GEMM partials
// =====================================================================
__global__ __launch_bounds__(512, 2) void k_hidden(const float* __restrict__ hw)
{
    __shared__ float vs_s[BB * IC];
    __shared__ float ps[BB * DD];
    const int i0 = blockIdx.x * IC;
    const int tid = threadIdx.x;
    const int d = tid & 255, g = tid >> 8;

    for (int idx = tid; idx < BB * IC; idx += 512) {
        int bb = idx >> 6, ii = idx & 63;
        vs_s[idx] = g_vladn[(size_t)bb * (KK * CC) + i0 + ii];
    }
    __syncthreads();

    float P[BB];
#pragma unroll
    for (int bb = 0; bb < BB; bb++) P[bb] = 0.f;

    const float* wp = hw + (size_t)(i0 + g * 32) * DD + d;
#pragma unroll
    for (int i = 0; i < 32; ++i) {
        float w = wp[(size_t)i * DD];
        int ii = g * 32 + i;
#pragma unroll
        for (int bb = 0; bb < BB; bb++) P[bb] = fmaf(vs_s[bb * IC + ii], w, P[bb]);
    }

    if (g == 1) {
#pragma unroll
        for (int bb = 0; bb < BB; bb++) ps[bb * DD + d] = P[bb];
    }
    __syncthreads();
    if (g == 0) {
#pragma unroll
        for (int bb = 0; bb < BB; bb++)
            g_hpart[((size_t)blockIdx.x * BB + bb) * DD + d] = P[bb] + ps[bb * DD + d];
    }
}

// =====================================================================
// Kernel 4: reduce hidden partials + global inv-norm
// =====================================================================
__global__ __launch_bounds__(256) void k_hreduce()
{
    __shared__ float red[8 * 33];
    const int b = blockIdx.y, dg = blockIdx.x;
    const int dl = threadIdx.x & 31, s8 = threadIdx.x >> 5;
    const int d = dg * 32 + dl;

    float inv = 0.f;
    if (s8 == 0) {
        float s = g_rsq[b * KK + dl] + g_rsq[b * KK + 32 + dl];
#pragma unroll
        for (int o = 16; o; o >>= 1) s += __shfl_xor_sync(0xffffffffu, s, o);
        inv = 1.0f / fmaxf(sqrtf(s), 1e-12f);
    }

    float s = 0.f;
#pragma unroll 8
    for (int ch = s8; ch < HCH; ch += 8)
        s += g_hpart[((size_t)ch * BB + b) * DD + d];
    red[s8 * 33 + dl] = s;
    __syncthreads();
    if (s8 == 0) {
        float t = 0.f;
#pragma unroll
        for (int w = 0; w < 8; w++) t += red[w * 33 + dl];
        g_h[b * DD + d] = t * inv;
    }
}

// =====================================================================
// Kernel 5/6/7: BN2, gating GEMM, final
// =====================================================================
__global__ __launch_bounds__(DD) void k_bn2(const float* __restrict__ gamma,
                                            const float* __restrict__ beta)
{
    const int d = threadIdx.x;
    float y[BB];
    float m = 0.f;
#pragma unroll
    for (int b = 0; b < BB; b++) { y[b] = g_h[b * DD + d]; m += y[b]; }
    m *= (1.0f / BB);
    float v = 0.f;
#pragma unroll
    for (int b = 0; b < BB; b++) { float dv = y[b] - m; v = fmaf(dv, dv, v); }
    v *= (1.0f / BB);
    float rs = 1.0f / sqrtf(v + 1e-5f);
    float ga = gamma[d], be = beta[d];
#pragma unroll
    for (int b = 0; b < BB; b++)
        g_y[b * DD + d] = ga * (y[b] - m) * rs + be;
}

__global__ __launch_bounds__(DD) void k_gate(const float* __restrict__ gw)
{
    __shared__ float yb[DD];
    const int b = blockIdx.x, d = threadIdx.x;
    yb[d] = g_y[b * DD + d];
    __syncthreads();
    float z = 0.f;
#pragma unroll 4
    for (int dd = 0; dd < DD; ++dd) z = fmaf(yb[dd], gw[dd * DD + d], z);
    g_z[b * DD + d] = z;
}

__global__ __launch_bounds__(DD) void k_final(const float* __restrict__ gbn_g,
                                              const float* __restrict__ gbn_b,
                                              float* __restrict__ out)
{
    const int d = threadIdx.x;
    float z[BB];
    float m = 0.f;
#pragma unroll
    for (int b = 0; b < BB; b++) { z[b] = g_z[b * DD + d]; m += z[b]; }
    m *= (1.0f / BB);
    float v = 0.f;
#pragma unroll
    for (int b = 0; b < BB; b++) { float dv = z[b] - m; v = fmaf(dv, dv, v); }
    v *= (1.0f / BB);
    float rs = 1.0f / sqrtf(v + 1e-5f);
    float gg = gbn_g[d], gb = gbn_b[d];
#pragma unroll
    for (int b = 0; b < BB; b++) {
        float zn = gg * (z[b] - m) * rs + gb;
        float gate = 1.0f / (1.0f + expf(-zn));
        out[b * DD + d] = g_y[b * DD + d] * gate;
    }
}

// =====================================================================
extern "C" void kernel_launch(void* const* d_in, const int* in_sizes, int n_in,
                              void* d_out, int out_size)
{
    (void)in_sizes; (void)n_in; (void)out_size;
    const float* x      = (const float*)d_in[0];
    const float* conv_w = (const float*)d_in[1];
    const float* cent   = (const float*)d_in[2];
    const float* hw     = (const float*)d_in[3];
    const float* gw     = (const float*)d_in[4];
    const float* bn2g   = (const float*)d_in[5];
    const float* bn2b   = (const float*)d_in[6];
    const float* gbng   = (const float*)d_in[7];
    const float* gbnb   = (const float*)d_in[8];
    float* out = (float*)d_out;

    cudaFuncSetAttribute(k_logits, cudaFuncAttributeMaxDynamicSharedMemorySize, SM_TOTAL);
    cudaFuncSetAttribute(k_vlad_t, cudaFuncAttributeMaxDynamicSharedMemorySize, SV_TOTAL);

    // launch idx 3 = k_logits (ncu capture slot); k_wtb idempotent pads
    k_wtb<<<(KK * CC + 255) / 256, 256>>>(conv_w);
    k_wtb<<<(KK * CC + 255) / 256, 256>>>(conv_w);
    k_wtb<<<(KK * CC + 255) / 256, 256>>>(conv_w);
    k_logits<<<dim3(NT128, BB), 128, SM_TOTAL>>>(x);
    k_vlad_t<<<dim3(SLB, BB), 256, SV_TOTAL>>>(x);
    k_reduce<<<dim3(KK, BB), 256>>>(cent);
    k_hidden<<<HCH, 512>>>(hw);
    k_hreduce<<<dim3(8, BB), 256>>>();
    k_bn2<<<1, DD>>>(bn2g, bn2b);
    k_gate<<<BB, DD>>>(gw);
    k_final<<<1, DD>>>(gbng, gbnb, out);
}